// round 10
// baseline (speedup 1.0000x reference)
#include <cuda_runtime.h>
#include <cuda_bf16.h>
#include <cstdint>
#include <cstddef>

// ===================== problem constants =====================
static constexpr int IN_F    = 4096;
static constexpr int OUT_F   = 4096;
static constexpr int RANK    = 16;
static constexpr int M_TOTAL = 4 * 2048;     // 8192 rows of x

static constexpr int THREADS = 256;

// ---- tcgen05 path tiling: CTA computes 256x256 (two 128-row M-tiles, shared W) ----
static constexpr int NT_TC = 256;
static constexpr int KC_TC = 32;             // K per stage; row = [hi 64B | lo 64B] = 128B SW128
static constexpr int NK_TC = IN_F / KC_TC;   // 128
// stage layout: A0 rows 0-127 @0 (16KB), A1 rows 128-255 @16K, W 256 rows @32K (32KB)
static constexpr int SW_OFF  = 32768;
static constexpr int STG_TC  = 65536;
// header: [0,16) tmem ptr, [64, 64+128*8) load mbarriers, [2048, 2048+128*8) mma mbarriers
static constexpr int HDR_TC  = 4096;
static constexpr int NSTAGE  = 3;
static constexpr int SMEM_DYN = HDR_TC + NSTAGE * STG_TC;   // 200704

// idesc: kind::f16, bf16 x bf16 -> f32, M=128, N=256, K-major both
static constexpr uint32_t IDESC_TC =
    (1u << 4) | (1u << 7) | (1u << 10) | ((NT_TC / 8u) << 17) | ((128 / 16u) << 24);

// ---- fallback (mma.sync): 4 tiles of 128x128 per CTA ----
static constexpr int KC_FB = 32;
static constexpr int NK_FB = IN_F / KC_FB;   // 128
static constexpr int ROWH  = 40;             // padded row stride in bf16 (80 B)
static constexpr int AH_B  = 0;
static constexpr int AL_B  = 128 * ROWH * 2;
static constexpr int BH_B  = 2 * 128 * ROWH * 2;
static constexpr int BL_B  = 3 * 128 * ROWH * 2;
static constexpr int STG_FB = 4 * 128 * ROWH * 2;    // 40960
static constexpr int NSTAGE_FB = 3;                  // 122880 <= SMEM_DYN

// ===================== scratch (__device__ globals; no cudaMalloc) ===========
__device__ __nv_bfloat16 g_Wh[(size_t)OUT_F * IN_F];
__device__ __nv_bfloat16 g_Wl[(size_t)OUT_F * IN_F];
__device__ __nv_bfloat16 g_Xh[(size_t)M_TOTAL * IN_F];
__device__ __nv_bfloat16 g_Xl[(size_t)M_TOTAL * IN_F];

// ===================== common helpers =====================
__device__ __forceinline__ uint32_t smem_u32(const void* p) {
    uint32_t a;
    asm("{ .reg .u64 t; cvta.to.shared.u64 t, %1; cvt.u32.u64 %0, t; }" : "=r"(a) : "l"(p));
    return a;
}
__device__ __forceinline__ void cp16(uint32_t sdst, const void* gsrc) {
    asm volatile("cp.async.cg.shared.global [%0], [%1], 16;" :: "r"(sdst), "l"(gsrc));
}
#define CP_COMMIT() asm volatile("cp.async.commit_group;" ::: "memory")
#define CP_WAIT(n)  asm volatile("cp.async.wait_group %0;" :: "n"(n) : "memory")

__device__ __forceinline__ void split2bf(float v, uint16_t& h, uint16_t& l) {
    __nv_bfloat16 hb = __float2bfloat16(v);
    float r = v - __bfloat162float(hb);
    __nv_bfloat16 lb = __float2bfloat16(r);
    h = *reinterpret_cast<uint16_t*>(&hb);
    l = *reinterpret_cast<uint16_t*>(&lb);
}
__device__ __forceinline__ uint32_t pr(uint16_t lo, uint16_t hi) {
    return (uint32_t)lo | ((uint32_t)hi << 16);
}
__device__ __forceinline__ uint32_t swz(uint32_t off) { return off ^ ((off >> 3) & 0x70); }

// ===================== tcgen05 machinery (sm_103a cubin only) ================
#if defined(__CUDA_ARCH_FEAT_SM103_ALL)
__device__ __forceinline__ uint32_t elect_one() {
    uint32_t p;
    asm volatile("{\n\t.reg .pred p;\n\telect.sync _|p, 0xFFFFFFFF;\n\tselp.b32 %0, 1, 0, p;\n\t}"
                 : "=r"(p));
    return p;
}
#define MBARRIER_INIT(addr, cnt) \
    asm volatile("mbarrier.init.shared.b64 [%0], %1;" :: "r"(addr), "r"(cnt) : "memory")
#define MBARRIER_WAIT_PARITY(mbar, par) do {                                             \
    uint32_t _m = (uint32_t)(mbar); uint32_t _p = (uint32_t)(par); uint32_t _d;          \
    asm volatile("{\n\t.reg .pred p;\n\t"                                                \
        "mbarrier.try_wait.parity.acquire.cta.shared::cta.b64 p, [%1], %2;\n\t"          \
        "selp.b32 %0, 1, 0, p;\n\t}" : "=r"(_d) : "r"(_m), "r"(_p) : "memory");          \
    if (!_d) {                                                                           \
        asm volatile("{\n\t.reg .pred P1;\n\tWL_%=: \n\t"                                \
            "mbarrier.try_wait.parity.acquire.cta.shared::cta.b64 P1, [%0], %1, 0x989680;\n\t" \
            "@P1 bra.uni WD_%=;\n\tbra.uni WL_%=;\n\tWD_%=: \n\t}"                       \
            :: "r"(_m), "r"(_p) : "memory");                                             \
    }                                                                                    \
} while (0)
// deferred arrive WITHOUT incrementing pending count (.noinc): counts against the
// initialized expect-count. (Default variant is net-zero on the phase -> deadlock.)
#define CP_ARRIVE(mbar) \
    asm volatile("cp.async.mbarrier.arrive.noinc.shared.b64 [%0];" :: "r"((uint32_t)(mbar)) : "memory")
#define TCGEN05_ALLOC(sa, n)  asm volatile("tcgen05.alloc.cta_group::1.sync.aligned.shared::cta.b32 [%0], %1;" :: "r"((uint32_t)(sa)), "r"((uint32_t)(n)) : "memory")
#define TCGEN05_RELQ()        asm volatile("tcgen05.relinquish_alloc_permit.cta_group::1.sync.aligned;")
#define TCGEN05_DEALLOC(t, n) asm volatile("tcgen05.dealloc.cta_group::1.sync.aligned.b32 %0, %1;" :: "r"(t), "r"((uint32_t)(n)))
#define TCGEN05_COMMIT(mb)    asm volatile("tcgen05.commit.cta_group::1.mbarrier::arrive::one.shared::cluster.b64 [%0];" :: "r"((uint32_t)(mb)) : "memory")
#define TCGEN05_FENCE_AFTER()  asm volatile("tcgen05.fence::after_thread_sync;" ::: "memory")
#define TCGEN05_FENCE_BEFORE() asm volatile("tcgen05.fence::before_thread_sync;" ::: "memory")
#define TCGEN05_WAIT_LD()      asm volatile("tcgen05.wait::ld.sync.aligned;" ::: "memory")
#define FENCE_PROXY()          asm volatile("fence.proxy.async.shared::cta;" ::: "memory")

#define TCGEN05_LD_X32(r, ta) \
    asm volatile( \
        "tcgen05.ld.sync.aligned.32x32b.x32.b32 " \
        "{%0, %1, %2, %3, %4, %5, %6, %7, " \
        " %8, %9, %10, %11, %12, %13, %14, %15, " \
        " %16, %17, %18, %19, %20, %21, %22, %23, " \
        " %24, %25, %26, %27, %28, %29, %30, %31}, [%32];" \
        : "=r"((r)[0]),  "=r"((r)[1]),  "=r"((r)[2]),  "=r"((r)[3]), \
          "=r"((r)[4]),  "=r"((r)[5]),  "=r"((r)[6]),  "=r"((r)[7]), \
          "=r"((r)[8]),  "=r"((r)[9]),  "=r"((r)[10]), "=r"((r)[11]), \
          "=r"((r)[12]), "=r"((r)[13]), "=r"((r)[14]), "=r"((r)[15]), \
          "=r"((r)[16]), "=r"((r)[17]), "=r"((r)[18]), "=r"((r)[19]), \
          "=r"((r)[20]), "=r"((r)[21]), "=r"((r)[22]), "=r"((r)[23]), \
          "=r"((r)[24]), "=r"((r)[25]), "=r"((r)[26]), "=r"((r)[27]), \
          "=r"((r)[28]), "=r"((r)[29]), "=r"((r)[30]), "=r"((r)[31]) \
        : "r"(ta))

static constexpr uint64_t SMEM_DESC_BASE_SW128 =
    (uint64_t(2) << 61) | (uint64_t(1) << 46) | (uint64_t(64) << 32) | (uint64_t(1) << 16);
#define MAKE_SMEM_DESC(ba) (SMEM_DESC_BASE_SW128 | ((uint64_t)((ba) >> 4) & 0x3FFF))

__device__ __forceinline__ void mma_f16_ss(uint32_t d, uint64_t a, uint64_t b,
                                           uint32_t idesc, uint32_t acc) {
    asm volatile(
        "{\n\t.reg .pred p;\n\tsetp.ne.u32 p, %4, 0;\n\t"
        "tcgen05.mma.cta_group::1.kind::f16 [%0], %1, %2, %3, {%5, %5, %5, %5}, p;\n\t}"
        :: "r"(d), "l"(a), "l"(b), "r"(idesc), "r"(acc), "r"(0u) : "memory");
}
#else
// family-pass only: ldmatrix/mma.sync helpers
__device__ __forceinline__ void ldm4(uint32_t* r, uint32_t addr) {
    asm volatile("ldmatrix.sync.aligned.m8n8.x4.shared.b16 {%0,%1,%2,%3}, [%4];"
                 : "=r"(r[0]), "=r"(r[1]), "=r"(r[2]), "=r"(r[3]) : "r"(addr));
}
__device__ __forceinline__ void mma16816(float* d, const uint32_t* a, const uint32_t* b) {
    asm volatile(
        "mma.sync.aligned.m16n8k16.row.col.f32.bf16.bf16.f32 "
        "{%0,%1,%2,%3}, {%4,%5,%6,%7}, {%8,%9}, {%0,%1,%2,%3};"
        : "+f"(d[0]), "+f"(d[1]), "+f"(d[2]), "+f"(d[3])
        : "r"(a[0]), "r"(a[1]), "r"(a[2]), "r"(a[3]), "r"(b[0]), "r"(b[1]));
}
#endif

// ===================== prep: x -> bf16 hi/lo =====================
__global__ void __launch_bounds__(256) prep_x(const float* __restrict__ x) {
    size_t i0 = ((size_t)blockIdx.x * 256 + threadIdx.x) * 8;
    float4 a = *reinterpret_cast<const float4*>(x + i0);
    float4 b = *reinterpret_cast<const float4*>(x + i0 + 4);
    float v[8] = {a.x, a.y, a.z, a.w, b.x, b.y, b.z, b.w};
    uint16_t h[8], l[8];
    #pragma unroll
    for (int e = 0; e < 8; ++e) split2bf(v[e], h[e], l[e]);
    *reinterpret_cast<uint4*>(&g_Xh[i0]) =
        make_uint4(pr(h[0], h[1]), pr(h[2], h[3]), pr(h[4], h[5]), pr(h[6], h[7]));
    *reinterpret_cast<uint4*>(&g_Xl[i0]) =
        make_uint4(pr(l[0], l[1]), pr(l[2], l[3]), pr(l[4], l[5]), pr(l[6], l[7]));
}

// ===================== prep: W' = W + (U*s)V^T -> bf16 hi/lo ==================
__global__ void __launch_bounds__(256) prep_w(
    const float* __restrict__ W, const float* __restrict__ U,
    const float* __restrict__ s, const float* __restrict__ V)
{
    __shared__ float Us[64][16];
    const int tid    = threadIdx.x;
    const int o_base = blockIdx.y * 64;
    const int i_base = blockIdx.x * 256;

    for (int t = tid; t < 64 * 16; t += 256) {
        int ol = t >> 4, r = t & 15;
        Us[ol][r] = U[(size_t)(o_base + ol) * RANK + r] * s[r];
    }
    const int i = i_base + tid;
    float4 q0 = *reinterpret_cast<const float4*>(V + (size_t)i * RANK + 0);
    float4 q1 = *reinterpret_cast<const float4*>(V + (size_t)i * RANK + 4);
    float4 q2 = *reinterpret_cast<const float4*>(V + (size_t)i * RANK + 8);
    float4 q3 = *reinterpret_cast<const float4*>(V + (size_t)i * RANK + 12);
    float vr[16] = {q0.x, q0.y, q0.z, q0.w, q1.x, q1.y, q1.z, q1.w,
                    q2.x, q2.y, q2.z, q2.w, q3.x, q3.y, q3.z, q3.w};
    __syncthreads();

    for (int ol = 0; ol < 64; ++ol) {
        const int o = o_base + ol;
        float acc = W[(size_t)o * IN_F + i];
        #pragma unroll
        for (int r = 0; r < 16; ++r) acc += Us[ol][r] * vr[r];
        uint16_t h, l;
        split2bf(acc, h, l);
        g_Wh[(size_t)o * IN_F + i] = *reinterpret_cast<__nv_bfloat16*>(&h);
        g_Wl[(size_t)o * IN_F + i] = *reinterpret_cast<__nv_bfloat16*>(&l);
    }
}

// ===================== GEMM kernel =====================
// grid (16, 32), 256 threads. TC path: 256x256 per CTA (two M-tiles, shared W).
__global__ void __launch_bounds__(THREADS, 1) gemm_kernel(float* __restrict__ out)
{
    extern __shared__ char smem[];
    const uint32_t sb = smem_u32(smem);
    const int tid  = threadIdx.x;
    const int lane = tid & 31;
    const int wid  = tid >> 5;
    const int m_base = blockIdx.y * 256;

#if defined(__CUDA_ARCH_FEAT_SM103_ALL)
    // ===================== tcgen05 path =====================
    const int n_base = blockIdx.x * NT_TC;
    const uint32_t MBL = sb + 64;             // 128 load mbarriers (count 256)
    const uint32_t MBM = sb + 2048;           // 128 mma-done mbarriers (count 1)

    if (tid == 0) {
        for (int i = 0; i < NK_TC; ++i) {
            MBARRIER_INIT(MBL + i * 8, THREADS);
            MBARRIER_INIT(MBM + i * 8, 1);
        }
    }
    if (wid == 0) {                           // alloc THEN relinquish (no race)
        TCGEN05_ALLOC(sb + 0, 512);
        TCGEN05_RELQ();
    }
    __syncthreads();
    uint32_t tmem;
    asm volatile("ld.shared.b32 %0, [%1];" : "=r"(tmem) : "r"(sb + 0));

    // stage fill: 4096 16B chunks (A: 256 rows, W: 256 rows; row = [hi 64B | lo 64B])
    auto issue = [&](int st, int kidx) {
        const uint32_t stb = sb + HDR_TC + st * STG_TC;
        const int k0 = kidx * KC_TC;
        #pragma unroll
        for (int j = 0; j < 16; ++j) {
            int t    = tid + j * 256;
            int row  = t >> 3;                 // 0..511
            int ch   = t & 7;
            int half = ch >> 2;                // 0 = hi, 1 = lo
            int c    = ch & 3;                 // 16B chunk within 64B
            uint32_t within = swz((uint32_t)((row & 255) * 128 + half * 64 + c * 16));
            if (row < 256) {                   // A (both m-tiles, contiguous 32KB)
                const __nv_bfloat16* src = half ? g_Xl : g_Xh;
                cp16(stb + within, src + (size_t)(m_base + row) * IN_F + k0 + c * 8);
            } else {                           // W
                const __nv_bfloat16* src = half ? g_Wl : g_Wh;
                cp16(stb + SW_OFF + within, src + (size_t)(n_base + (row - 256)) * IN_F + k0 + c * 8);
            }
        }
    };

    // prologue: stages 0,1 in flight, completion tracked by load mbarriers
    issue(0, 0); CP_ARRIVE(MBL + 0 * 8);
    issue(1, 1); CP_ARRIVE(MBL + 1 * 8);

    for (int it = 0; it < NK_TC; ++it) {
        const int cur = it % NSTAGE;

        // 1) MMA(it): elect lane waits the load barrier (2 iters of slack), issues 12 MMAs
        if (wid == 0) {
            if (elect_one()) {
                MBARRIER_WAIT_PARITY(MBL + it * 8, 0);
                FENCE_PROXY();
                TCGEN05_FENCE_AFTER();
                const uint32_t stb = sb + HDR_TC + cur * STG_TC;
                const uint64_t dW  = MAKE_SMEM_DESC(stb + SW_OFF);
                const uint32_t first = (it == 0) ? 0u : 1u;
                #pragma unroll
                for (int mt = 0; mt < 2; ++mt) {
                    const uint64_t dA = MAKE_SMEM_DESC(stb + mt * 16384);
                    const uint32_t D  = tmem + mt * 256;
                    mma_f16_ss(D, dA + 0, dW + 0, IDESC_TC, first);  // xh*Wh k0
                    mma_f16_ss(D, dA + 2, dW + 2, IDESC_TC, 1u);     // xh*Wh k1
                    mma_f16_ss(D, dA + 0, dW + 4, IDESC_TC, 1u);     // xh*Wl k0
                    mma_f16_ss(D, dA + 2, dW + 6, IDESC_TC, 1u);     // xh*Wl k1
                    mma_f16_ss(D, dA + 4, dW + 0, IDESC_TC, 1u);     // xl*Wh k0
                    mma_f16_ss(D, dA + 6, dW + 2, IDESC_TC, 1u);     // xl*Wh k1
                }
                TCGEN05_COMMIT(MBM + it * 8);
            }
        }

        // 2) producers: free stage (it+2)%3 by waiting MMA(it-1), then refill it
        if (it + 2 < NK_TC) {
            if (it >= 1) MBARRIER_WAIT_PARITY(MBM + (it - 1) * 8, 0);
            issue((it + 2) % NSTAGE, it + 2);
            CP_ARRIVE(MBL + (it + 2) * 8);
        }
    }
    MBARRIER_WAIT_PARITY(MBM + (NK_TC - 1) * 8, 0);
    TCGEN05_FENCE_AFTER();

    // epilogue: warp w: rows (w&3)*32+lane of each m-tile, col half (w>>2)*128
    {
        const int sub = wid & 3;
        const int q   = wid >> 2;
        #pragma unroll
        for (int mt = 0; mt < 2; ++mt) {
            const int row = m_base + mt * 128 + sub * 32 + lane;
            #pragma unroll
            for (int cc = 0; cc < 4; ++cc) {
                uint32_t regs[32];
                const uint32_t col0 = (uint32_t)(q * 128 + cc * 32);
                TCGEN05_LD_X32(regs, tmem + mt * 256 + col0);
                TCGEN05_WAIT_LD();
                float* dst = out + (size_t)row * OUT_F + n_base + col0;
                #pragma unroll
                for (int j = 0; j < 32; j += 4)
                    *reinterpret_cast<float4*>(dst + j) =
                        make_float4(__uint_as_float(regs[j]), __uint_as_float(regs[j + 1]),
                                    __uint_as_float(regs[j + 2]), __uint_as_float(regs[j + 3]));
            }
        }
    }
    TCGEN05_FENCE_BEFORE();
    __syncthreads();
    if (wid == 0) TCGEN05_DEALLOC(tmem, 512);

#else
    // ===================== fallback (mma.sync), 4 tiles of 128x128 =============
    const int wm = wid & 3;
    const int wn = wid >> 2;

    for (int mhalf = 0; mhalf < 2; ++mhalf)
    for (int nhalf = 0; nhalf < 2; ++nhalf) {
        const int mb = m_base + mhalf * 128;
        const int n_base_fb = (blockIdx.x * 2 + nhalf) * 128;
        __syncthreads();   // protect stage reuse across tiles

        auto issue = [&](int st, int kidx) {
            const uint32_t stb = sb + st * STG_FB;
            const int k0 = kidx * KC_FB;
            const int r0 = tid >> 2, c = tid & 3;
            #pragma unroll
            for (int j = 0; j < 2; ++j) {
                int r = r0 + j * 64;
                uint32_t rowoff = (uint32_t)(r * (ROWH * 2) + c * 16);
                size_t gx = (size_t)(mb + r) * IN_F + k0 + c * 8;
                size_t gw = (size_t)(n_base_fb + r) * IN_F + k0 + c * 8;
                cp16(stb + AH_B + rowoff, &g_Xh[gx]);
                cp16(stb + AL_B + rowoff, &g_Xl[gx]);
                cp16(stb + BH_B + rowoff, &g_Wh[gw]);
                cp16(stb + BL_B + rowoff, &g_Wl[gw]);
            }
        };

        issue(0, 0); CP_COMMIT();
        issue(1, 1); CP_COMMIT();

        float acc[2][8][4];
        #pragma unroll
        for (int a = 0; a < 2; ++a)
            #pragma unroll
            for (int b = 0; b < 8; ++b)
                #pragma unroll
                for (int cidx = 0; cidx < 4; ++cidx) acc[a][b][cidx] = 0.f;

        const int aRow  = wm * 32 + (lane & 15);
        const int aColH = (lane >> 4) * 8;
        const int bIdx  = lane & 7;
        const int bGrp  = lane >> 3;
        const int bRow  = wn * 64 + ((bGrp & 2) << 2) + bIdx;
        const int bColH = (bGrp & 1) * 8;

        for (int i = 0; i < NK_FB; ++i) {
            CP_WAIT(1);
            __syncthreads();
            if (i + 2 < NK_FB) issue((i + 2) % NSTAGE_FB, i + 2);
            CP_COMMIT();

            const uint32_t stb = sb + (i % NSTAGE_FB) * STG_FB;
            #pragma unroll
            for (int k16 = 0; k16 < 2; ++k16) {
                uint32_t ah[2][4], al[2][4];
                #pragma unroll
                for (int mt = 0; mt < 2; ++mt) {
                    uint32_t off = (uint32_t)((aRow + mt * 16) * (ROWH * 2) +
                                              (k16 * 16 + aColH) * 2);
                    ldm4(ah[mt], stb + AH_B + off);
                    ldm4(al[mt], stb + AL_B + off);
                }
                #pragma unroll
                for (int j = 0; j < 4; ++j) {
                    uint32_t off = (uint32_t)((bRow + j * 16) * (ROWH * 2) +
                                              (k16 * 16 + bColH) * 2);
                    uint32_t bh[4];
                    ldm4(bh, stb + BH_B + off);
                    #pragma unroll
                    for (int mt = 0; mt < 2; ++mt) {
                        mma16816(acc[mt][2 * j + 0], ah[mt], bh + 0);
                        mma16816(acc[mt][2 * j + 1], ah[mt], bh + 2);
                        mma16816(acc[mt][2 * j + 0], al[mt], bh + 0);
                        mma16816(acc[mt][2 * j + 1], al[mt], bh + 2);
                    }
                }
                #pragma unroll
                for (int j = 0; j < 4; ++j) {
                    uint32_t off = (uint32_t)((bRow + j * 16) * (ROWH * 2) +
                                              (k16 * 16 + bColH) * 2);
                    uint32_t bl[4];
                    ldm4(bl, stb + BL_B + off);
                    #pragma unroll
                    for (int mt = 0; mt < 2; ++mt) {
                        mma16816(acc[mt][2 * j + 0], ah[mt], bl + 0);
                        mma16816(acc[mt][2 * j + 1], ah[mt], bl + 2);
                    }
                }
            }
        }

        #pragma unroll
        for (int mt = 0; mt < 2; ++mt) {
            const int row0 = mb + wm * 32 + mt * 16 + (lane >> 2);
            #pragma unroll
            for (int nb = 0; nb < 8; ++nb) {
                const int col = n_base_fb + wn * 64 + nb * 8 + (lane & 3) * 2;
                *reinterpret_cast<float2*>(out + (size_t)row0 * OUT_F + col) =
                    make_float2(acc[mt][nb][0], acc[mt][nb][1]);
                *reinterpret_cast<float2*>(out + (size_t)(row0 + 8) * OUT_F + col) =
                    make_float2(acc[mt][nb][2], acc[mt][nb][3]);
            }
        }
    }
#endif
}

// ===================== harness entry =====================
extern "C" void kernel_launch(void* const* d_in, const int* in_sizes, int n_in,
                              void* d_out, int out_size)
{
    const float* x = (const float*)d_in[0];
    const float* W = (const float*)d_in[1];
    const float* U = (const float*)d_in[2];
    const float* s = (const float*)d_in[3];
    const float* V = (const float*)d_in[4];
    float* out = (float*)d_out;
    (void)in_sizes; (void)n_in; (void)out_size;

    prep_x<<<(M_TOTAL * IN_F) / (256 * 8), 256>>>(x);
    prep_w<<<dim3(IN_F / 256, OUT_F / 64), 256>>>(W, U, s, V);

    cudaFuncSetAttribute(gemm_kernel, cudaFuncAttributeMaxDynamicSharedMemorySize, SMEM_DYN);
    gemm_kernel<<<dim3(OUT_F / NT_TC, M_TOTAL / 256), THREADS, SMEM_DYN>>>(out);
}

// round 11
// speedup vs baseline: 1.1061x; 1.1061x over previous
#include <cuda_runtime.h>
#include <cuda.h>
#include <cuda_bf16.h>
#include <cstdint>
#include <cstddef>

// ===================== problem constants =====================
static constexpr int IN_F    = 4096;
static constexpr int OUT_F   = 4096;
static constexpr int RANK    = 16;
static constexpr int M_TOTAL = 4 * 2048;     // 8192 rows of x
static constexpr int PK      = 2 * IN_F;     // packed K (hi|lo interleaved per 32-group) = 8192

static constexpr int THREADS = 256;

// ---- tcgen05 path: CTA 256x256 (two 128-row M-tiles, shared W), KC=32 ----
static constexpr int NT_TC = 256;
static constexpr int KC_TC = 32;             // k-elems per stage; packed row chunk = 128B
static constexpr int NK_TC = IN_F / KC_TC;   // 128
// stage: X 256 rows x 128B @0 (32KB), W 256 rows x 128B @32K (32KB)
static constexpr int SW_OFF  = 32768;
static constexpr int STG_TC  = 65536;
// header: [0,16) tmem ptr, [64,1088) full mbars, [2048,3072) mma mbars
static constexpr int HDR_TC  = 4096;
static constexpr int NSTAGE  = 3;
static constexpr int SMEM_DYN = HDR_TC + NSTAGE * STG_TC;   // 200704

// idesc: kind::f16, bf16 x bf16 -> f32, M=128, N=256, K-major both
static constexpr uint32_t IDESC_TC =
    (1u << 4) | (1u << 7) | (1u << 10) | ((NT_TC / 8u) << 17) | ((128 / 16u) << 24);

// ---- fallback (mma.sync): 4 tiles of 128x128 per CTA ----
static constexpr int KC_FB = 32;
static constexpr int NK_FB = IN_F / KC_FB;   // 128
static constexpr int ROWH  = 40;             // padded row stride in bf16 (80 B)
static constexpr int AH_B  = 0;
static constexpr int AL_B  = 128 * ROWH * 2;
static constexpr int BH_B  = 2 * 128 * ROWH * 2;
static constexpr int BL_B  = 3 * 128 * ROWH * 2;
static constexpr int STG_FB = 4 * 128 * ROWH * 2;    // 40960
static constexpr int NSTAGE_FB = 3;

// ===================== scratch (__device__ globals; no cudaMalloc) ===========
// packed layout: row r, k-group g (32 elems): [hi(32 bf16) | lo(32 bf16)] at cols g*64..g*64+63
__device__ __nv_bfloat16 g_Xp[(size_t)M_TOTAL * PK];   // 128 MB
__device__ __nv_bfloat16 g_Wp[(size_t)OUT_F * PK];     // 64 MB

// ===================== common helpers =====================
__device__ __forceinline__ uint32_t smem_u32(const void* p) {
    uint32_t a;
    asm("{ .reg .u64 t; cvta.to.shared.u64 t, %1; cvt.u32.u64 %0, t; }" : "=r"(a) : "l"(p));
    return a;
}
__device__ __forceinline__ void cp16(uint32_t sdst, const void* gsrc) {
    asm volatile("cp.async.cg.shared.global [%0], [%1], 16;" :: "r"(sdst), "l"(gsrc));
}
#define CP_COMMIT() asm volatile("cp.async.commit_group;" ::: "memory")
#define CP_WAIT(n)  asm volatile("cp.async.wait_group %0;" :: "n"(n) : "memory")

__device__ __forceinline__ void split2bf(float v, uint16_t& h, uint16_t& l) {
    __nv_bfloat16 hb = __float2bfloat16(v);
    float r = v - __bfloat162float(hb);
    __nv_bfloat16 lb = __float2bfloat16(r);
    h = *reinterpret_cast<uint16_t*>(&hb);
    l = *reinterpret_cast<uint16_t*>(&lb);
}
__device__ __forceinline__ uint32_t pr(uint16_t lo, uint16_t hi) {
    return (uint32_t)lo | ((uint32_t)hi << 16);
}

// ===================== tcgen05/TMA machinery (sm_103a cubin only) =============
#if defined(__CUDA_ARCH_FEAT_SM103_ALL)
__device__ __forceinline__ uint32_t elect_one() {
    uint32_t p;
    asm volatile("{\n\t.reg .pred p;\n\telect.sync _|p, 0xFFFFFFFF;\n\tselp.b32 %0, 1, 0, p;\n\t}"
                 : "=r"(p));
    return p;
}
#define MBARRIER_INIT(addr, cnt) \
    asm volatile("mbarrier.init.shared.b64 [%0], %1;" :: "r"(addr), "r"(cnt) : "memory")
#define MBARRIER_EXPECT_TX(mbar, bytes) \
    asm volatile("mbarrier.arrive.expect_tx.shared.b64 _, [%0], %1;" \
                 :: "r"((uint32_t)(mbar)), "r"((uint32_t)(bytes)) : "memory")
#define MBARRIER_WAIT_PARITY(mbar, par) do {                                             \
    uint32_t _m = (uint32_t)(mbar); uint32_t _p = (uint32_t)(par); uint32_t _d;          \
    asm volatile("{\n\t.reg .pred p;\n\t"                                                \
        "mbarrier.try_wait.parity.acquire.cta.shared::cta.b64 p, [%1], %2;\n\t"          \
        "selp.b32 %0, 1, 0, p;\n\t}" : "=r"(_d) : "r"(_m), "r"(_p) : "memory");          \
    if (!_d) {                                                                           \
        asm volatile("{\n\t.reg .pred P1;\n\tWL_%=: \n\t"                                \
            "mbarrier.try_wait.parity.acquire.cta.shared::cta.b64 P1, [%0], %1, 0x989680;\n\t" \
            "@P1 bra.uni WD_%=;\n\tbra.uni WL_%=;\n\tWD_%=: \n\t}"                       \
            :: "r"(_m), "r"(_p) : "memory");                                             \
    }                                                                                    \
} while (0)
#define TMA_LOAD_2D(smem, mapp, c0, c1, mbar) \
    asm volatile("cp.async.bulk.tensor.2d.shared::cta.global.tile.mbarrier::complete_tx::bytes " \
                 "[%0], [%1, {%2, %3}], [%4];" \
                 :: "r"((uint32_t)(smem)), "l"(mapp), "r"((int)(c0)), "r"((int)(c1)), \
                    "r"((uint32_t)(mbar)) : "memory")
#define TCGEN05_ALLOC(sa, n)  asm volatile("tcgen05.alloc.cta_group::1.sync.aligned.shared::cta.b32 [%0], %1;" :: "r"((uint32_t)(sa)), "r"((uint32_t)(n)) : "memory")
#define TCGEN05_RELQ()        asm volatile("tcgen05.relinquish_alloc_permit.cta_group::1.sync.aligned;")
#define TCGEN05_DEALLOC(t, n) asm volatile("tcgen05.dealloc.cta_group::1.sync.aligned.b32 %0, %1;" :: "r"(t), "r"((uint32_t)(n)))
#define TCGEN05_COMMIT(mb)    asm volatile("tcgen05.commit.cta_group::1.mbarrier::arrive::one.shared::cluster.b64 [%0];" :: "r"((uint32_t)(mb)) : "memory")
#define TCGEN05_FENCE_AFTER()  asm volatile("tcgen05.fence::after_thread_sync;" ::: "memory")
#define TCGEN05_FENCE_BEFORE() asm volatile("tcgen05.fence::before_thread_sync;" ::: "memory")
#define TCGEN05_WAIT_LD()      asm volatile("tcgen05.wait::ld.sync.aligned;" ::: "memory")

#define TCGEN05_LD_X32(r, ta) \
    asm volatile( \
        "tcgen05.ld.sync.aligned.32x32b.x32.b32 " \
        "{%0, %1, %2, %3, %4, %5, %6, %7, " \
        " %8, %9, %10, %11, %12, %13, %14, %15, " \
        " %16, %17, %18, %19, %20, %21, %22, %23, " \
        " %24, %25, %26, %27, %28, %29, %30, %31}, [%32];" \
        : "=r"((r)[0]),  "=r"((r)[1]),  "=r"((r)[2]),  "=r"((r)[3]), \
          "=r"((r)[4]),  "=r"((r)[5]),  "=r"((r)[6]),  "=r"((r)[7]), \
          "=r"((r)[8]),  "=r"((r)[9]),  "=r"((r)[10]), "=r"((r)[11]), \
          "=r"((r)[12]), "=r"((r)[13]), "=r"((r)[14]), "=r"((r)[15]), \
          "=r"((r)[16]), "=r"((r)[17]), "=r"((r)[18]), "=r"((r)[19]), \
          "=r"((r)[20]), "=r"((r)[21]), "=r"((r)[22]), "=r"((r)[23]), \
          "=r"((r)[24]), "=r"((r)[25]), "=r"((r)[26]), "=r"((r)[27]), \
          "=r"((r)[28]), "=r"((r)[29]), "=r"((r)[30]), "=r"((r)[31]) \
        : "r"(ta))

static constexpr uint64_t SMEM_DESC_BASE_SW128 =
    (uint64_t(2) << 61) | (uint64_t(1) << 46) | (uint64_t(64) << 32) | (uint64_t(1) << 16);
#define MAKE_SMEM_DESC(ba) (SMEM_DESC_BASE_SW128 | ((uint64_t)((ba) >> 4) & 0x3FFF))

__device__ __forceinline__ void mma_f16_ss(uint32_t d, uint64_t a, uint64_t b,
                                           uint32_t idesc, uint32_t acc) {
    asm volatile(
        "{\n\t.reg .pred p;\n\tsetp.ne.u32 p, %4, 0;\n\t"
        "tcgen05.mma.cta_group::1.kind::f16 [%0], %1, %2, %3, {%5, %5, %5, %5}, p;\n\t}"
        :: "r"(d), "l"(a), "l"(b), "r"(idesc), "r"(acc), "r"(0u) : "memory");
}
#else
// family-pass only: ldmatrix/mma.sync helpers
__device__ __forceinline__ void ldm4(uint32_t* r, uint32_t addr) {
    asm volatile("ldmatrix.sync.aligned.m8n8.x4.shared.b16 {%0,%1,%2,%3}, [%4];"
                 : "=r"(r[0]), "=r"(r[1]), "=r"(r[2]), "=r"(r[3]) : "r"(addr));
}
__device__ __forceinline__ void mma16816(float* d, const uint32_t* a, const uint32_t* b) {
    asm volatile(
        "mma.sync.aligned.m16n8k16.row.col.f32.bf16.bf16.f32 "
        "{%0,%1,%2,%3}, {%4,%5,%6,%7}, {%8,%9}, {%0,%1,%2,%3};"
        : "+f"(d[0]), "+f"(d[1]), "+f"(d[2]), "+f"(d[3])
        : "r"(a[0]), "r"(a[1]), "r"(a[2]), "r"(a[3]), "r"(b[0]), "r"(b[1]));
}
#endif

// ===================== prep: x -> packed bf16 [hi32|lo32] per 32-group =========
__global__ void __launch_bounds__(256) prep_x(const float* __restrict__ x) {
    size_t i0  = ((size_t)blockIdx.x * 256 + threadIdx.x) * 8;   // flat over 8192*4096
    size_t row = i0 >> 12;
    int    k   = (int)(i0 & 4095);
    float4 a = *reinterpret_cast<const float4*>(x + i0);
    float4 b = *reinterpret_cast<const float4*>(x + i0 + 4);
    float v[8] = {a.x, a.y, a.z, a.w, b.x, b.y, b.z, b.w};
    uint16_t h[8], l[8];
    #pragma unroll
    for (int e = 0; e < 8; ++e) split2bf(v[e], h[e], l[e]);
    size_t base = row * PK + (size_t)(k >> 5) * 64 + (k & 31);
    *reinterpret_cast<uint4*>(&g_Xp[base]) =
        make_uint4(pr(h[0], h[1]), pr(h[2], h[3]), pr(h[4], h[5]), pr(h[6], h[7]));
    *reinterpret_cast<uint4*>(&g_Xp[base + 32]) =
        make_uint4(pr(l[0], l[1]), pr(l[2], l[3]), pr(l[4], l[5]), pr(l[6], l[7]));
}

// ===================== prep: W' = W + (U*s)V^T -> packed bf16 ==================
__global__ void __launch_bounds__(256) prep_w(
    const float* __restrict__ W, const float* __restrict__ U,
    const float* __restrict__ s, const float* __restrict__ V)
{
    __shared__ float Us[64][16];
    const int tid    = threadIdx.x;
    const int o_base = blockIdx.y * 64;
    const int i_base = blockIdx.x * 256;

    for (int t = tid; t < 64 * 16; t += 256) {
        int ol = t >> 4, r = t & 15;
        Us[ol][r] = U[(size_t)(o_base + ol) * RANK + r] * s[r];
    }
    const int i = i_base + tid;
    float4 q0 = *reinterpret_cast<const float4*>(V + (size_t)i * RANK + 0);
    float4 q1 = *reinterpret_cast<const float4*>(V + (size_t)i * RANK + 4);
    float4 q2 = *reinterpret_cast<const float4*>(V + (size_t)i * RANK + 8);
    float4 q3 = *reinterpret_cast<const float4*>(V + (size_t)i * RANK + 12);
    float vr[16] = {q0.x, q0.y, q0.z, q0.w, q1.x, q1.y, q1.z, q1.w,
                    q2.x, q2.y, q2.z, q2.w, q3.x, q3.y, q3.z, q3.w};
    __syncthreads();

    const size_t col_h = (size_t)(i >> 5) * 64 + (i & 31);
    for (int ol = 0; ol < 64; ++ol) {
        const int o = o_base + ol;
        float acc = W[(size_t)o * IN_F + i];
        #pragma unroll
        for (int r = 0; r < 16; ++r) acc += Us[ol][r] * vr[r];
        uint16_t h, l;
        split2bf(acc, h, l);
        g_Wp[(size_t)o * PK + col_h]      = *reinterpret_cast<__nv_bfloat16*>(&h);
        g_Wp[(size_t)o * PK + col_h + 32] = *reinterpret_cast<__nv_bfloat16*>(&l);
    }
}

// ===================== GEMM kernel =====================
// grid (16, 32), 256 threads. TC path: 256x256 per CTA; TMA + single-thread pipeline.
__global__ void __launch_bounds__(THREADS, 1) gemm_kernel(
    float* __restrict__ out,
    const __grid_constant__ CUtensorMap tmx,
    const __grid_constant__ CUtensorMap tmw)
{
    extern __shared__ char smem[];
    const uint32_t sb = smem_u32(smem);
    const int tid  = threadIdx.x;
    const int lane = tid & 31;
    const int wid  = tid >> 5;
    const int m_base = blockIdx.y * 256;

#if defined(__CUDA_ARCH_FEAT_SM103_ALL)
    // ===================== tcgen05 + TMA path =====================
    const int n_base = blockIdx.x * NT_TC;
    const uint32_t FULL = sb + 64;            // 128 TMA-complete mbarriers (count 1)
    const uint32_t MBM  = sb + 2048;          // 128 mma-done mbarriers (count 1)

    if (tid == 0) {
        for (int i = 0; i < NK_TC; ++i) {
            MBARRIER_INIT(FULL + i * 8, 1);
            MBARRIER_INIT(MBM + i * 8, 1);
        }
    }
    if (wid == 0) {                           // alloc THEN relinquish (no race)
        TCGEN05_ALLOC(sb + 0, 512);
        TCGEN05_RELQ();
    }
    __syncthreads();
    uint32_t tmem;
    asm volatile("ld.shared.b32 %0, [%1];" : "=r"(tmem) : "r"(sb + 0));

    if (wid == 0) {
        if (elect_one()) {
            // prologue: stages 0,1 in flight
            #pragma unroll
            for (int p = 0; p < 2; ++p) {
                const uint32_t stb = sb + HDR_TC + p * STG_TC;
                MBARRIER_EXPECT_TX(FULL + p * 8, STG_TC);
                TMA_LOAD_2D(stb,          &tmx, 64 * p, m_base, FULL + p * 8);
                TMA_LOAD_2D(stb + SW_OFF, &tmw, 64 * p, n_base, FULL + p * 8);
            }
            for (int it = 0; it < NK_TC; ++it) {
                const int cur = it % NSTAGE;
                // 1) wait TMA(it), issue 12 MMAs — keeps tensor queue fed
                MBARRIER_WAIT_PARITY(FULL + it * 8, 0);
                const uint32_t stb = sb + HDR_TC + cur * STG_TC;
                const uint64_t dW  = MAKE_SMEM_DESC(stb + SW_OFF);
                const uint32_t first = (it == 0) ? 0u : 1u;
                #pragma unroll
                for (int mt = 0; mt < 2; ++mt) {
                    const uint64_t dA = MAKE_SMEM_DESC(stb + mt * 16384);
                    const uint32_t D  = tmem + mt * 256;
                    mma_f16_ss(D, dA + 0, dW + 0, IDESC_TC, first);  // xh*Wh k0
                    mma_f16_ss(D, dA + 2, dW + 2, IDESC_TC, 1u);     // xh*Wh k1
                    mma_f16_ss(D, dA + 0, dW + 4, IDESC_TC, 1u);     // xh*Wl k0
                    mma_f16_ss(D, dA + 2, dW + 6, IDESC_TC, 1u);     // xh*Wl k1
                    mma_f16_ss(D, dA + 4, dW + 0, IDESC_TC, 1u);     // xl*Wh k0
                    mma_f16_ss(D, dA + 6, dW + 2, IDESC_TC, 1u);     // xl*Wh k1
                }
                TCGEN05_COMMIT(MBM + it * 8);
                // 2) free stage (it+2)%3 (used by MMA(it-1)), refill via TMA
                if (it + 2 < NK_TC) {
                    if (it >= 1) MBARRIER_WAIT_PARITY(MBM + (it - 1) * 8, 0);
                    const uint32_t nb = sb + HDR_TC + ((it + 2) % NSTAGE) * STG_TC;
                    MBARRIER_EXPECT_TX(FULL + (it + 2) * 8, STG_TC);
                    TMA_LOAD_2D(nb,          &tmx, 64 * (it + 2), m_base, FULL + (it + 2) * 8);
                    TMA_LOAD_2D(nb + SW_OFF, &tmw, 64 * (it + 2), n_base, FULL + (it + 2) * 8);
                }
            }
        }
    }
    // all threads: wait for the last MMA
    MBARRIER_WAIT_PARITY(MBM + (NK_TC - 1) * 8, 0);
    TCGEN05_FENCE_AFTER();

    // epilogue: warp w: rows (w&3)*32+lane of each m-tile, col half (w>>2)*128
    {
        const int sub = wid & 3;
        const int q   = wid >> 2;
        #pragma unroll
        for (int mt = 0; mt < 2; ++mt) {
            const int row = m_base + mt * 128 + sub * 32 + lane;
            #pragma unroll
            for (int cc = 0; cc < 4; ++cc) {
                uint32_t regs[32];
                const uint32_t col0 = (uint32_t)(q * 128 + cc * 32);
                TCGEN05_LD_X32(regs, tmem + mt * 256 + col0);
                TCGEN05_WAIT_LD();
                float* dst = out + (size_t)row * OUT_F + n_base + col0;
                #pragma unroll
                for (int j = 0; j < 32; j += 4)
                    *reinterpret_cast<float4*>(dst + j) =
                        make_float4(__uint_as_float(regs[j]), __uint_as_float(regs[j + 1]),
                                    __uint_as_float(regs[j + 2]), __uint_as_float(regs[j + 3]));
            }
        }
    }
    TCGEN05_FENCE_BEFORE();
    __syncthreads();
    if (wid == 0) TCGEN05_DEALLOC(tmem, 512);

#else
    // ===================== fallback (mma.sync), 4 tiles of 128x128 =============
    const int wm = wid & 3;
    const int wn = wid >> 2;

    for (int mhalf = 0; mhalf < 2; ++mhalf)
    for (int nhalf = 0; nhalf < 2; ++nhalf) {
        const int mb = m_base + mhalf * 128;
        const int n_base_fb = (blockIdx.x * 2 + nhalf) * 128;
        __syncthreads();   // protect stage reuse across tiles

        auto issue = [&](int st, int kidx) {
            const uint32_t stb = sb + st * STG_FB;
            const int g = kidx;                  // KC_FB = 32 -> group index = kidx
            const int r0 = tid >> 2, c = tid & 3;
            #pragma unroll
            for (int j = 0; j < 2; ++j) {
                int r = r0 + j * 64;
                uint32_t rowoff = (uint32_t)(r * (ROWH * 2) + c * 16);
                size_t bx = (size_t)(mb + r) * PK + (size_t)g * 64 + c * 8;
                size_t bw = (size_t)(n_base_fb + r) * PK + (size_t)g * 64 + c * 8;
                cp16(stb + AH_B + rowoff, &g_Xp[bx]);
                cp16(stb + AL_B + rowoff, &g_Xp[bx + 32]);
                cp16(stb + BH_B + rowoff, &g_Wp[bw]);
                cp16(stb + BL_B + rowoff, &g_Wp[bw + 32]);
            }
        };

        issue(0, 0); CP_COMMIT();
        issue(1, 1); CP_COMMIT();

        float acc[2][8][4];
        #pragma unroll
        for (int a = 0; a < 2; ++a)
            #pragma unroll
            for (int b = 0; b < 8; ++b)
                #pragma unroll
                for (int cidx = 0; cidx < 4; ++cidx) acc[a][b][cidx] = 0.f;

        const int aRow  = wm * 32 + (lane & 15);
        const int aColH = (lane >> 4) * 8;
        const int bIdx  = lane & 7;
        const int bGrp  = lane >> 3;
        const int bRow  = wn * 64 + ((bGrp & 2) << 2) + bIdx;
        const int bColH = (bGrp & 1) * 8;

        for (int i = 0; i < NK_FB; ++i) {
            CP_WAIT(1);
            __syncthreads();
            if (i + 2 < NK_FB) issue((i + 2) % NSTAGE_FB, i + 2);
            CP_COMMIT();

            const uint32_t stb = sb + (i % NSTAGE_FB) * STG_FB;
            #pragma unroll
            for (int k16 = 0; k16 < 2; ++k16) {
                uint32_t ah[2][4], al[2][4];
                #pragma unroll
                for (int mt = 0; mt < 2; ++mt) {
                    uint32_t off = (uint32_t)((aRow + mt * 16) * (ROWH * 2) +
                                              (k16 * 16 + aColH) * 2);
                    ldm4(ah[mt], stb + AH_B + off);
                    ldm4(al[mt], stb + AL_B + off);
                }
                #pragma unroll
                for (int j = 0; j < 4; ++j) {
                    uint32_t off = (uint32_t)((bRow + j * 16) * (ROWH * 2) +
                                              (k16 * 16 + bColH) * 2);
                    uint32_t bh[4];
                    ldm4(bh, stb + BH_B + off);
                    #pragma unroll
                    for (int mt = 0; mt < 2; ++mt) {
                        mma16816(acc[mt][2 * j + 0], ah[mt], bh + 0);
                        mma16816(acc[mt][2 * j + 1], ah[mt], bh + 2);
                        mma16816(acc[mt][2 * j + 0], al[mt], bh + 0);
                        mma16816(acc[mt][2 * j + 1], al[mt], bh + 2);
                    }
                }
                #pragma unroll
                for (int j = 0; j < 4; ++j) {
                    uint32_t off = (uint32_t)((bRow + j * 16) * (ROWH * 2) +
                                              (k16 * 16 + bColH) * 2);
                    uint32_t bl[4];
                    ldm4(bl, stb + BL_B + off);
                    #pragma unroll
                    for (int mt = 0; mt < 2; ++mt) {
                        mma16816(acc[mt][2 * j + 0], ah[mt], bl + 0);
                        mma16816(acc[mt][2 * j + 1], ah[mt], bl + 2);
                    }
                }
            }
        }

        #pragma unroll
        for (int mt = 0; mt < 2; ++mt) {
            const int row0 = mb + wm * 32 + mt * 16 + (lane >> 2);
            #pragma unroll
            for (int nb = 0; nb < 8; ++nb) {
                const int col = n_base_fb + wn * 64 + nb * 8 + (lane & 3) * 2;
                *reinterpret_cast<float2*>(out + (size_t)row0 * OUT_F + col) =
                    make_float2(acc[mt][nb][0], acc[mt][nb][1]);
                *reinterpret_cast<float2*>(out + (size_t)(row0 + 8) * OUT_F + col) =
                    make_float2(acc[mt][nb][2], acc[mt][nb][3]);
            }
        }
    }
#endif
}

// ===================== harness entry =====================
typedef CUresult (*PFN_encodeTiled_t)(
    CUtensorMap*, CUtensorMapDataType, cuuint32_t, void*,
    const cuuint64_t*, const cuuint64_t*, const cuuint32_t*, const cuuint32_t*,
    CUtensorMapInterleave, CUtensorMapSwizzle, CUtensorMapL2promotion,
    CUtensorMapFloatOOBfill);

extern "C" void kernel_launch(void* const* d_in, const int* in_sizes, int n_in,
                              void* d_out, int out_size)
{
    const float* x = (const float*)d_in[0];
    const float* W = (const float*)d_in[1];
    const float* U = (const float*)d_in[2];
    const float* s = (const float*)d_in[3];
    const float* V = (const float*)d_in[4];
    float* out = (float*)d_out;
    (void)in_sizes; (void)n_in; (void)out_size;

    prep_x<<<(M_TOTAL * IN_F) / (256 * 8), 256>>>(x);
    prep_w<<<dim3(IN_F / 256, OUT_F / 64), 256>>>(W, U, s, V);

    // build TMA descriptors (host-side, no allocation, graph-capture safe)
    alignas(64) CUtensorMap tmx{}, tmw{};
    {
        void* px = nullptr; cudaGetSymbolAddress(&px, g_Xp);
        void* pw = nullptr; cudaGetSymbolAddress(&pw, g_Wp);
        PFN_encodeTiled_t enc = nullptr;
        cudaDriverEntryPointQueryResult st{};
        cudaGetDriverEntryPoint("cuTensorMapEncodeTiled", (void**)&enc,
                                cudaEnableDefault, &st);
        if (enc) {
            cuuint64_t dimsX[2] = {(cuuint64_t)PK, (cuuint64_t)M_TOTAL};
            cuuint64_t strX[1]  = {(cuuint64_t)PK * 2};
            cuuint32_t box[2]   = {64, 256};
            cuuint32_t es[2]    = {1, 1};
            enc(&tmx, CU_TENSOR_MAP_DATA_TYPE_BFLOAT16, 2, px, dimsX, strX, box, es,
                CU_TENSOR_MAP_INTERLEAVE_NONE, CU_TENSOR_MAP_SWIZZLE_128B,
                CU_TENSOR_MAP_L2_PROMOTION_L2_128B, CU_TENSOR_MAP_FLOAT_OOB_FILL_NONE);
            cuuint64_t dimsW[2] = {(cuuint64_t)PK, (cuuint64_t)OUT_F};
            cuuint64_t strW[1]  = {(cuuint64_t)PK * 2};
            enc(&tmw, CU_TENSOR_MAP_DATA_TYPE_BFLOAT16, 2, pw, dimsW, strW, box, es,
                CU_TENSOR_MAP_INTERLEAVE_NONE, CU_TENSOR_MAP_SWIZZLE_128B,
                CU_TENSOR_MAP_L2_PROMOTION_L2_128B, CU_TENSOR_MAP_FLOAT_OOB_FILL_NONE);
        }
    }

    cudaFuncSetAttribute(gemm_kernel, cudaFuncAttributeMaxDynamicSharedMemorySize, SMEM_DYN);
    gemm_kernel<<<dim3(OUT_F / NT_TC, M_TOTAL / 256), THREADS, SMEM_DYN>>>(out, tmx, tmw);
}

// round 12
// speedup vs baseline: 1.1172x; 1.0101x over previous
#include <cuda_runtime.h>
#include <cuda.h>
#include <cuda_bf16.h>
#include <cstdint>
#include <cstddef>

// ===================== problem constants =====================
static constexpr int IN_F    = 4096;
static constexpr int OUT_F   = 4096;
static constexpr int RANK    = 16;
static constexpr int M_TOTAL = 4 * 2048;     // 8192 rows of x
static constexpr int PK      = 2 * IN_F;     // packed K (hi|lo interleaved per 32-group) = 8192

static constexpr int THREADS = 256;

// ---- tcgen05 path: CTA 256x256 (two 128-row M-tiles, shared W), KC=32 ----
static constexpr int NT_TC = 256;
static constexpr int KC_TC = 32;             // k-elems per stage; packed row chunk = 128B
static constexpr int NK_TC = IN_F / KC_TC;   // 128
// stage: X 256 rows x 128B @0 (32KB), W 256 rows x 128B @32K (32KB)
static constexpr int SW_OFF  = 32768;
static constexpr int STG_TC  = 65536;
// header: [0,16) tmem ptr, [64,1088) full mbars, [2048,3072) mma mbars
static constexpr int HDR_TC  = 4096;
static constexpr int NSTAGE  = 3;
static constexpr int SMEM_DYN = HDR_TC + NSTAGE * STG_TC;   // 200704

// idesc: kind::f16, bf16 x bf16 -> f32, M=128, N=256, K-major both
static constexpr uint32_t IDESC_TC =
    (1u << 4) | (1u << 7) | (1u << 10) | ((NT_TC / 8u) << 17) | ((128 / 16u) << 24);

// ---- fallback (mma.sync): 4 tiles of 128x128 per CTA ----
static constexpr int KC_FB = 32;
static constexpr int NK_FB = IN_F / KC_FB;   // 128
static constexpr int ROWH  = 40;             // padded row stride in bf16 (80 B)
static constexpr int AH_B  = 0;
static constexpr int AL_B  = 128 * ROWH * 2;
static constexpr int BH_B  = 2 * 128 * ROWH * 2;
static constexpr int BL_B  = 3 * 128 * ROWH * 2;
static constexpr int STG_FB = 4 * 128 * ROWH * 2;    // 40960
static constexpr int NSTAGE_FB = 3;

// ===================== scratch (__device__ globals; no cudaMalloc) ===========
// packed layout: row r, k-group g (32 elems): [hi(32 bf16) | lo(32 bf16)] at cols g*64..g*64+63
__device__ __nv_bfloat16 g_Xp[(size_t)M_TOTAL * PK];   // 128 MB
__device__ __nv_bfloat16 g_Wp[(size_t)OUT_F * PK];     // 64 MB

// ===================== common helpers =====================
__device__ __forceinline__ uint32_t smem_u32(const void* p) {
    uint32_t a;
    asm("{ .reg .u64 t; cvta.to.shared.u64 t, %1; cvt.u32.u64 %0, t; }" : "=r"(a) : "l"(p));
    return a;
}
__device__ __forceinline__ void cp16(uint32_t sdst, const void* gsrc) {
    asm volatile("cp.async.cg.shared.global [%0], [%1], 16;" :: "r"(sdst), "l"(gsrc));
}
#define CP_COMMIT() asm volatile("cp.async.commit_group;" ::: "memory")
#define CP_WAIT(n)  asm volatile("cp.async.wait_group %0;" :: "n"(n) : "memory")

__device__ __forceinline__ void split2bf(float v, uint16_t& h, uint16_t& l) {
    __nv_bfloat16 hb = __float2bfloat16(v);
    float r = v - __bfloat162float(hb);
    __nv_bfloat16 lb = __float2bfloat16(r);
    h = *reinterpret_cast<uint16_t*>(&hb);
    l = *reinterpret_cast<uint16_t*>(&lb);
}
__device__ __forceinline__ uint32_t pr(uint16_t lo, uint16_t hi) {
    return (uint32_t)lo | ((uint32_t)hi << 16);
}

// ===================== tcgen05/TMA machinery (sm_103a cubin only) =============
#if defined(__CUDA_ARCH_FEAT_SM103_ALL)
__device__ __forceinline__ uint32_t elect_one() {
    uint32_t p;
    asm volatile("{\n\t.reg .pred p;\n\telect.sync _|p, 0xFFFFFFFF;\n\tselp.b32 %0, 1, 0, p;\n\t}"
                 : "=r"(p));
    return p;
}
#define MBARRIER_INIT(addr, cnt) \
    asm volatile("mbarrier.init.shared.b64 [%0], %1;" :: "r"(addr), "r"(cnt) : "memory")
#define MBARRIER_EXPECT_TX(mbar, bytes) \
    asm volatile("mbarrier.arrive.expect_tx.shared.b64 _, [%0], %1;" \
                 :: "r"((uint32_t)(mbar)), "r"((uint32_t)(bytes)) : "memory")
#define MBARRIER_WAIT_PARITY(mbar, par) do {                                             \
    uint32_t _m = (uint32_t)(mbar); uint32_t _p = (uint32_t)(par); uint32_t _d;          \
    asm volatile("{\n\t.reg .pred p;\n\t"                                                \
        "mbarrier.try_wait.parity.acquire.cta.shared::cta.b64 p, [%1], %2;\n\t"          \
        "selp.b32 %0, 1, 0, p;\n\t}" : "=r"(_d) : "r"(_m), "r"(_p) : "memory");          \
    if (!_d) {                                                                           \
        asm volatile("{\n\t.reg .pred P1;\n\tWL_%=: \n\t"                                \
            "mbarrier.try_wait.parity.acquire.cta.shared::cta.b64 P1, [%0], %1, 0x989680;\n\t" \
            "@P1 bra.uni WD_%=;\n\tbra.uni WL_%=;\n\tWD_%=: \n\t}"                       \
            :: "r"(_m), "r"(_p) : "memory");                                             \
    }                                                                                    \
} while (0)
#define TMA_LOAD_2D(smem, mapp, c0, c1, mbar) \
    asm volatile("cp.async.bulk.tensor.2d.shared::cta.global.tile.mbarrier::complete_tx::bytes " \
                 "[%0], [%1, {%2, %3}], [%4];" \
                 :: "r"((uint32_t)(smem)), "l"(mapp), "r"((int)(c0)), "r"((int)(c1)), \
                    "r"((uint32_t)(mbar)) : "memory")
#define TCGEN05_ALLOC(sa, n)  asm volatile("tcgen05.alloc.cta_group::1.sync.aligned.shared::cta.b32 [%0], %1;" :: "r"((uint32_t)(sa)), "r"((uint32_t)(n)) : "memory")
#define TCGEN05_RELQ()        asm volatile("tcgen05.relinquish_alloc_permit.cta_group::1.sync.aligned;")
#define TCGEN05_DEALLOC(t, n) asm volatile("tcgen05.dealloc.cta_group::1.sync.aligned.b32 %0, %1;" :: "r"(t), "r"((uint32_t)(n)))
#define TCGEN05_COMMIT(mb)    asm volatile("tcgen05.commit.cta_group::1.mbarrier::arrive::one.shared::cluster.b64 [%0];" :: "r"((uint32_t)(mb)) : "memory")
#define TCGEN05_FENCE_AFTER()  asm volatile("tcgen05.fence::after_thread_sync;" ::: "memory")
#define TCGEN05_FENCE_BEFORE() asm volatile("tcgen05.fence::before_thread_sync;" ::: "memory")
#define TCGEN05_WAIT_LD()      asm volatile("tcgen05.wait::ld.sync.aligned;" ::: "memory")

#define TCGEN05_LD_X32(r, ta) \
    asm volatile( \
        "tcgen05.ld.sync.aligned.32x32b.x32.b32 " \
        "{%0, %1, %2, %3, %4, %5, %6, %7, " \
        " %8, %9, %10, %11, %12, %13, %14, %15, " \
        " %16, %17, %18, %19, %20, %21, %22, %23, " \
        " %24, %25, %26, %27, %28, %29, %30, %31}, [%32];" \
        : "=r"((r)[0]),  "=r"((r)[1]),  "=r"((r)[2]),  "=r"((r)[3]), \
          "=r"((r)[4]),  "=r"((r)[5]),  "=r"((r)[6]),  "=r"((r)[7]), \
          "=r"((r)[8]),  "=r"((r)[9]),  "=r"((r)[10]), "=r"((r)[11]), \
          "=r"((r)[12]), "=r"((r)[13]), "=r"((r)[14]), "=r"((r)[15]), \
          "=r"((r)[16]), "=r"((r)[17]), "=r"((r)[18]), "=r"((r)[19]), \
          "=r"((r)[20]), "=r"((r)[21]), "=r"((r)[22]), "=r"((r)[23]), \
          "=r"((r)[24]), "=r"((r)[25]), "=r"((r)[26]), "=r"((r)[27]), \
          "=r"((r)[28]), "=r"((r)[29]), "=r"((r)[30]), "=r"((r)[31]) \
        : "r"(ta))

static constexpr uint64_t SMEM_DESC_BASE_SW128 =
    (uint64_t(2) << 61) | (uint64_t(1) << 46) | (uint64_t(64) << 32) | (uint64_t(1) << 16);
#define MAKE_SMEM_DESC(ba) (SMEM_DESC_BASE_SW128 | ((uint64_t)((ba) >> 4) & 0x3FFF))

__device__ __forceinline__ void mma_f16_ss(uint32_t d, uint64_t a, uint64_t b,
                                           uint32_t idesc, uint32_t acc) {
    asm volatile(
        "{\n\t.reg .pred p;\n\tsetp.ne.u32 p, %4, 0;\n\t"
        "tcgen05.mma.cta_group::1.kind::f16 [%0], %1, %2, %3, {%5, %5, %5, %5}, p;\n\t}"
        :: "r"(d), "l"(a), "l"(b), "r"(idesc), "r"(acc), "r"(0u) : "memory");
}
#else
// family-pass only: ldmatrix/mma.sync helpers
__device__ __forceinline__ void ldm4(uint32_t* r, uint32_t addr) {
    asm volatile("ldmatrix.sync.aligned.m8n8.x4.shared.b16 {%0,%1,%2,%3}, [%4];"
                 : "=r"(r[0]), "=r"(r[1]), "=r"(r[2]), "=r"(r[3]) : "r"(addr));
}
__device__ __forceinline__ void mma16816(float* d, const uint32_t* a, const uint32_t* b) {
    asm volatile(
        "mma.sync.aligned.m16n8k16.row.col.f32.bf16.bf16.f32 "
        "{%0,%1,%2,%3}, {%4,%5,%6,%7}, {%8,%9}, {%0,%1,%2,%3};"
        : "+f"(d[0]), "+f"(d[1]), "+f"(d[2]), "+f"(d[3])
        : "r"(a[0]), "r"(a[1]), "r"(a[2]), "r"(a[3]), "r"(b[0]), "r"(b[1]));
}
#endif

// ===================== prep: x -> packed bf16 [hi32|lo32] per 32-group =========
__global__ void __launch_bounds__(256) prep_x(const float* __restrict__ x) {
    size_t i0  = ((size_t)blockIdx.x * 256 + threadIdx.x) * 8;   // flat over 8192*4096
    size_t row = i0 >> 12;
    int    k   = (int)(i0 & 4095);
    float4 a = *reinterpret_cast<const float4*>(x + i0);
    float4 b = *reinterpret_cast<const float4*>(x + i0 + 4);
    float v[8] = {a.x, a.y, a.z, a.w, b.x, b.y, b.z, b.w};
    uint16_t h[8], l[8];
    #pragma unroll
    for (int e = 0; e < 8; ++e) split2bf(v[e], h[e], l[e]);
    size_t base = row * PK + (size_t)(k >> 5) * 64 + (k & 31);
    *reinterpret_cast<uint4*>(&g_Xp[base]) =
        make_uint4(pr(h[0], h[1]), pr(h[2], h[3]), pr(h[4], h[5]), pr(h[6], h[7]));
    *reinterpret_cast<uint4*>(&g_Xp[base + 32]) =
        make_uint4(pr(l[0], l[1]), pr(l[2], l[3]), pr(l[4], l[5]), pr(l[6], l[7]));
}

// ===================== prep: W' = W + (U*s)V^T -> packed bf16 ==================
__global__ void __launch_bounds__(256) prep_w(
    const float* __restrict__ W, const float* __restrict__ U,
    const float* __restrict__ s, const float* __restrict__ V)
{
    __shared__ float Us[64][16];
    const int tid    = threadIdx.x;
    const int o_base = blockIdx.y * 64;
    const int i_base = blockIdx.x * 256;

    for (int t = tid; t < 64 * 16; t += 256) {
        int ol = t >> 4, r = t & 15;
        Us[ol][r] = U[(size_t)(o_base + ol) * RANK + r] * s[r];
    }
    const int i = i_base + tid;
    float4 q0 = *reinterpret_cast<const float4*>(V + (size_t)i * RANK + 0);
    float4 q1 = *reinterpret_cast<const float4*>(V + (size_t)i * RANK + 4);
    float4 q2 = *reinterpret_cast<const float4*>(V + (size_t)i * RANK + 8);
    float4 q3 = *reinterpret_cast<const float4*>(V + (size_t)i * RANK + 12);
    float vr[16] = {q0.x, q0.y, q0.z, q0.w, q1.x, q1.y, q1.z, q1.w,
                    q2.x, q2.y, q2.z, q2.w, q3.x, q3.y, q3.z, q3.w};
    __syncthreads();

    const size_t col_h = (size_t)(i >> 5) * 64 + (i & 31);
    for (int ol = 0; ol < 64; ++ol) {
        const int o = o_base + ol;
        float acc = W[(size_t)o * IN_F + i];
        #pragma unroll
        for (int r = 0; r < 16; ++r) acc += Us[ol][r] * vr[r];
        uint16_t h, l;
        split2bf(acc, h, l);
        g_Wp[(size_t)o * PK + col_h]      = *reinterpret_cast<__nv_bfloat16*>(&h);
        g_Wp[(size_t)o * PK + col_h + 32] = *reinterpret_cast<__nv_bfloat16*>(&l);
    }
}

// ===================== GEMM kernel =====================
// grid (16, 32), 256 threads. TC path: 256x256 per CTA; TMA + single-thread pipeline.
__global__ void __launch_bounds__(THREADS, 1) gemm_kernel(
    float* __restrict__ out,
    const __grid_constant__ CUtensorMap tmx,
    const __grid_constant__ CUtensorMap tmw)
{
    extern __shared__ char smem[];
    const uint32_t sb = smem_u32(smem);
    const int tid  = threadIdx.x;
    const int lane = tid & 31;
    const int wid  = tid >> 5;
    const int m_base = blockIdx.y * 256;

#if defined(__CUDA_ARCH_FEAT_SM103_ALL)
    // ===================== tcgen05 + TMA path =====================
    const int n_base = blockIdx.x * NT_TC;
    const uint32_t FULL = sb + 64;            // 128 TMA-complete mbarriers (count 1)
    const uint32_t MBM  = sb + 2048;          // 128 mma-done mbarriers (count 1)

    if (tid == 0) {
        for (int i = 0; i < NK_TC; ++i) {
            MBARRIER_INIT(FULL + i * 8, 1);
            MBARRIER_INIT(MBM + i * 8, 1);
        }
    }
    if (wid == 0) {                           // alloc THEN relinquish (no race)
        TCGEN05_ALLOC(sb + 0, 512);
        TCGEN05_RELQ();
    }
    __syncthreads();
    uint32_t tmem;
    asm volatile("ld.shared.b32 %0, [%1];" : "=r"(tmem) : "r"(sb + 0));

    if (wid == 0) {
        if (elect_one()) {
            // prologue: stages 0,1 in flight
            #pragma unroll
            for (int p = 0; p < 2; ++p) {
                const uint32_t stb = sb + HDR_TC + p * STG_TC;
                MBARRIER_EXPECT_TX(FULL + p * 8, STG_TC);
                TMA_LOAD_2D(stb,          &tmx, 64 * p, m_base, FULL + p * 8);
                TMA_LOAD_2D(stb + SW_OFF, &tmw, 64 * p, n_base, FULL + p * 8);
            }
            for (int it = 0; it < NK_TC; ++it) {
                const int cur = it % NSTAGE;
                // 1) wait TMA(it), issue 12 MMAs — keeps tensor queue fed
                MBARRIER_WAIT_PARITY(FULL + it * 8, 0);
                const uint32_t stb = sb + HDR_TC + cur * STG_TC;
                const uint64_t dW  = MAKE_SMEM_DESC(stb + SW_OFF);
                const uint32_t first = (it == 0) ? 0u : 1u;
                #pragma unroll
                for (int mt = 0; mt < 2; ++mt) {
                    const uint64_t dA = MAKE_SMEM_DESC(stb + mt * 16384);
                    const uint32_t D  = tmem + mt * 256;
                    mma_f16_ss(D, dA + 0, dW + 0, IDESC_TC, first);  // xh*Wh k0
                    mma_f16_ss(D, dA + 2, dW + 2, IDESC_TC, 1u);     // xh*Wh k1
                    mma_f16_ss(D, dA + 0, dW + 4, IDESC_TC, 1u);     // xh*Wl k0
                    mma_f16_ss(D, dA + 2, dW + 6, IDESC_TC, 1u);     // xh*Wl k1
                    mma_f16_ss(D, dA + 4, dW + 0, IDESC_TC, 1u);     // xl*Wh k0
                    mma_f16_ss(D, dA + 6, dW + 2, IDESC_TC, 1u);     // xl*Wh k1
                }
                TCGEN05_COMMIT(MBM + it * 8);
                // 2) free stage (it+2)%3 (used by MMA(it-1)), refill via TMA
                if (it + 2 < NK_TC) {
                    if (it >= 1) MBARRIER_WAIT_PARITY(MBM + (it - 1) * 8, 0);
                    const uint32_t nb = sb + HDR_TC + ((it + 2) % NSTAGE) * STG_TC;
                    MBARRIER_EXPECT_TX(FULL + (it + 2) * 8, STG_TC);
                    TMA_LOAD_2D(nb,          &tmx, 64 * (it + 2), m_base, FULL + (it + 2) * 8);
                    TMA_LOAD_2D(nb + SW_OFF, &tmw, 64 * (it + 2), n_base, FULL + (it + 2) * 8);
                }
            }
        }
    }
    // all threads: wait for the last MMA
    MBARRIER_WAIT_PARITY(MBM + (NK_TC - 1) * 8, 0);
    TCGEN05_FENCE_AFTER();

    // epilogue: warp w: rows (w&3)*32+lane of each m-tile, col half (w>>2)*128
    {
        const int sub = wid & 3;
        const int q   = wid >> 2;
        #pragma unroll
        for (int mt = 0; mt < 2; ++mt) {
            const int row = m_base + mt * 128 + sub * 32 + lane;
            #pragma unroll
            for (int cc = 0; cc < 4; ++cc) {
                uint32_t regs[32];
                const uint32_t col0 = (uint32_t)(q * 128 + cc * 32);
                TCGEN05_LD_X32(regs, tmem + mt * 256 + col0);
                TCGEN05_WAIT_LD();
                float* dst = out + (size_t)row * OUT_F + n_base + col0;
                #pragma unroll
                for (int j = 0; j < 32; j += 4)
                    *reinterpret_cast<float4*>(dst + j) =
                        make_float4(__uint_as_float(regs[j]), __uint_as_float(regs[j + 1]),
                                    __uint_as_float(regs[j + 2]), __uint_as_float(regs[j + 3]));
            }
        }
    }
    TCGEN05_FENCE_BEFORE();
    __syncthreads();
    if (wid == 0) TCGEN05_DEALLOC(tmem, 512);

#else
    // ===================== fallback (mma.sync), 4 tiles of 128x128 =============
    const int wm = wid & 3;
    const int wn = wid >> 2;

    for (int mhalf = 0; mhalf < 2; ++mhalf)
    for (int nhalf = 0; nhalf < 2; ++nhalf) {
        const int mb = m_base + mhalf * 128;
        const int n_base_fb = (blockIdx.x * 2 + nhalf) * 128;
        __syncthreads();   // protect stage reuse across tiles

        auto issue = [&](int st, int kidx) {
            const uint32_t stb = sb + st * STG_FB;
            const int g = kidx;                  // KC_FB = 32 -> group index = kidx
            const int r0 = tid >> 2, c = tid & 3;
            #pragma unroll
            for (int j = 0; j < 2; ++j) {
                int r = r0 + j * 64;
                uint32_t rowoff = (uint32_t)(r * (ROWH * 2) + c * 16);
                size_t bx = (size_t)(mb + r) * PK + (size_t)g * 64 + c * 8;
                size_t bw = (size_t)(n_base_fb + r) * PK + (size_t)g * 64 + c * 8;
                cp16(stb + AH_B + rowoff, &g_Xp[bx]);
                cp16(stb + AL_B + rowoff, &g_Xp[bx + 32]);
                cp16(stb + BH_B + rowoff, &g_Wp[bw]);
                cp16(stb + BL_B + rowoff, &g_Wp[bw + 32]);
            }
        };

        issue(0, 0); CP_COMMIT();
        issue(1, 1); CP_COMMIT();

        float acc[2][8][4];
        #pragma unroll
        for (int a = 0; a < 2; ++a)
            #pragma unroll
            for (int b = 0; b < 8; ++b)
                #pragma unroll
                for (int cidx = 0; cidx < 4; ++cidx) acc[a][b][cidx] = 0.f;

        const int aRow  = wm * 32 + (lane & 15);
        const int aColH = (lane >> 4) * 8;
        const int bIdx  = lane & 7;
        const int bGrp  = lane >> 3;
        const int bRow  = wn * 64 + ((bGrp & 2) << 2) + bIdx;
        const int bColH = (bGrp & 1) * 8;

        for (int i = 0; i < NK_FB; ++i) {
            CP_WAIT(1);
            __syncthreads();
            if (i + 2 < NK_FB) issue((i + 2) % NSTAGE_FB, i + 2);
            CP_COMMIT();

            const uint32_t stb = sb + (i % NSTAGE_FB) * STG_FB;
            #pragma unroll
            for (int k16 = 0; k16 < 2; ++k16) {
                uint32_t ah[2][4], al[2][4];
                #pragma unroll
                for (int mt = 0; mt < 2; ++mt) {
                    uint32_t off = (uint32_t)((aRow + mt * 16) * (ROWH * 2) +
                                              (k16 * 16 + aColH) * 2);
                    ldm4(ah[mt], stb + AH_B + off);
                    ldm4(al[mt], stb + AL_B + off);
                }
                #pragma unroll
                for (int j = 0; j < 4; ++j) {
                    uint32_t off = (uint32_t)((bRow + j * 16) * (ROWH * 2) +
                                              (k16 * 16 + bColH) * 2);
                    uint32_t bh[4];
                    ldm4(bh, stb + BH_B + off);
                    #pragma unroll
                    for (int mt = 0; mt < 2; ++mt) {
                        mma16816(acc[mt][2 * j + 0], ah[mt], bh + 0);
                        mma16816(acc[mt][2 * j + 1], ah[mt], bh + 2);
                        mma16816(acc[mt][2 * j + 0], al[mt], bh + 0);
                        mma16816(acc[mt][2 * j + 1], al[mt], bh + 2);
                    }
                }
                #pragma unroll
                for (int j = 0; j < 4; ++j) {
                    uint32_t off = (uint32_t)((bRow + j * 16) * (ROWH * 2) +
                                              (k16 * 16 + bColH) * 2);
                    uint32_t bl[4];
                    ldm4(bl, stb + BL_B + off);
                    #pragma unroll
                    for (int mt = 0; mt < 2; ++mt) {
                        mma16816(acc[mt][2 * j + 0], ah[mt], bl + 0);
                        mma16816(acc[mt][2 * j + 1], ah[mt], bl + 2);
                    }
                }
            }
        }

        #pragma unroll
        for (int mt = 0; mt < 2; ++mt) {
            const int row0 = mb + wm * 32 + mt * 16 + (lane >> 2);
            #pragma unroll
            for (int nb = 0; nb < 8; ++nb) {
                const int col = n_base_fb + wn * 64 + nb * 8 + (lane & 3) * 2;
                *reinterpret_cast<float2*>(out + (size_t)row0 * OUT_F + col) =
                    make_float2(acc[mt][nb][0], acc[mt][nb][1]);
                *reinterpret_cast<float2*>(out + (size_t)(row0 + 8) * OUT_F + col) =
                    make_float2(acc[mt][nb][2], acc[mt][nb][3]);
            }
        }
    }
#endif
}

// ===================== harness entry =====================
typedef CUresult (*PFN_encodeTiled_t)(
    CUtensorMap*, CUtensorMapDataType, cuuint32_t, void*,
    const cuuint64_t*, const cuuint64_t*, const cuuint32_t*, const cuuint32_t*,
    CUtensorMapInterleave, CUtensorMapSwizzle, CUtensorMapL2promotion,
    CUtensorMapFloatOOBfill);

extern "C" void kernel_launch(void* const* d_in, const int* in_sizes, int n_in,
                              void* d_out, int out_size)
{
    const float* x = (const float*)d_in[0];
    const float* W = (const float*)d_in[1];
    const float* U = (const float*)d_in[2];
    const float* s = (const float*)d_in[3];
    const float* V = (const float*)d_in[4];
    float* out = (float*)d_out;
    (void)in_sizes; (void)n_in; (void)out_size;

    prep_x<<<(M_TOTAL * IN_F) / (256 * 8), 256>>>(x);
    prep_w<<<dim3(IN_F / 256, OUT_F / 64), 256>>>(W, U, s, V);

    // build TMA descriptors (host-side, no allocation, graph-capture safe)
    alignas(64) CUtensorMap tmx{}, tmw{};
    {
        void* px = nullptr; cudaGetSymbolAddress(&px, g_Xp);
        void* pw = nullptr; cudaGetSymbolAddress(&pw, g_Wp);
        PFN_encodeTiled_t enc = nullptr;
        cudaDriverEntryPointQueryResult st{};
        cudaGetDriverEntryPoint("cuTensorMapEncodeTiled", (void**)&enc,
                                cudaEnableDefault, &st);
        if (enc) {
            cuuint64_t dimsX[2] = {(cuuint64_t)PK, (cuuint64_t)M_TOTAL};
            cuuint64_t strX[1]  = {(cuuint64_t)PK * 2};
            cuuint32_t box[2]   = {64, 256};
            cuuint32_t es[2]    = {1, 1};
            enc(&tmx, CU_TENSOR_MAP_DATA_TYPE_BFLOAT16, 2, px, dimsX, strX, box, es,
                CU_TENSOR_MAP_INTERLEAVE_NONE, CU_TENSOR_MAP_SWIZZLE_128B,
                CU_TENSOR_MAP_L2_PROMOTION_L2_128B, CU_TENSOR_MAP_FLOAT_OOB_FILL_NONE);
            cuuint64_t dimsW[2] = {(cuuint64_t)PK, (cuuint64_t)OUT_F};
            cuuint64_t strW[1]  = {(cuuint64_t)PK * 2};
            enc(&tmw, CU_TENSOR_MAP_DATA_TYPE_BFLOAT16, 2, pw, dimsW, strW, box, es,
                CU_TENSOR_MAP_INTERLEAVE_NONE, CU_TENSOR_MAP_SWIZZLE_128B,
                CU_TENSOR_MAP_L2_PROMOTION_L2_128B, CU_TENSOR_MAP_FLOAT_OOB_FILL_NONE);
        }
    }

    cudaFuncSetAttribute(gemm_kernel, cudaFuncAttributeMaxDynamicSharedMemorySize, SMEM_DYN);
    gemm_kernel<<<dim3(OUT_F / NT_TC, M_TOTAL / 256), THREADS, SMEM_DYN>>>(out, tmx, tmw);
}

// round 13
// speedup vs baseline: 1.1932x; 1.0680x over previous
#include <cuda_runtime.h>
#include <cuda.h>
#include <cuda_bf16.h>
#include <cstdint>
#include <cstddef>

// ===================== problem constants =====================
static constexpr int IN_F    = 4096;
static constexpr int OUT_F   = 4096;
static constexpr int RANK    = 16;
static constexpr int M_TOTAL = 4 * 2048;     // 8192 rows of x
static constexpr int PK      = 2 * IN_F;     // packed K (hi|lo per 32-group) = 8192

static constexpr int THREADS = 256;

// ---- tcgen05 cg2 path: 2-CTA cluster computes 256x256; each CTA M/2, N/2 ----
static constexpr int KC_TC = 32;             // k-elems per stage; packed chunk = 128B/row
static constexpr int NK_TC = IN_F / KC_TC;   // 128
// per-CTA stage: X slice 128 rows x 128B @0 (16KB), W slice 128 rows x 128B @16K (16KB)
static constexpr int SW_OFF  = 16384;
static constexpr int STG_TC  = 32768;
static constexpr int NSTAGE  = 5;
// header: [0,16) tmem ptr, [64,1088) FULL mbars, [2048,3072) MMA mbars
static constexpr int HDR_TC  = 4096;
static constexpr int SMEM_DYN = HDR_TC + NSTAGE * STG_TC;   // 167936

// idesc cg2 kind::f16: bf16 x bf16 -> f32, M=256, N=256, K-major both
static constexpr uint32_t IDESC_CG2 =
    (1u << 4) | (1u << 7) | (1u << 10) | ((256 / 8u) << 17) | ((256 / 16u) << 24);

// ---- fallback (mma.sync): per CTA 128 rows x 256 cols (two 128x128 tiles) ----
static constexpr int KC_FB = 32;
static constexpr int NK_FB = IN_F / KC_FB;   // 128
static constexpr int ROWH  = 40;             // padded row stride in bf16 (80 B)
static constexpr int AH_B  = 0;
static constexpr int AL_B  = 128 * ROWH * 2;
static constexpr int BH_B  = 2 * 128 * ROWH * 2;
static constexpr int BL_B  = 3 * 128 * ROWH * 2;
static constexpr int STG_FB = 4 * 128 * ROWH * 2;    // 40960
static constexpr int NSTAGE_FB = 3;                  // 122880 <= SMEM_DYN

// ===================== scratch (__device__ globals; no cudaMalloc) ===========
// packed: row r, k-group g: [hi(32 bf16) | lo(32 bf16)] at cols g*64..g*64+63
__device__ __nv_bfloat16 g_Xp[(size_t)M_TOTAL * PK];   // 128 MB
__device__ __nv_bfloat16 g_Wp[(size_t)OUT_F * PK];     // 64 MB

// ===================== common helpers =====================
__device__ __forceinline__ uint32_t smem_u32(const void* p) {
    uint32_t a;
    asm("{ .reg .u64 t; cvta.to.shared.u64 t, %1; cvt.u32.u64 %0, t; }" : "=r"(a) : "l"(p));
    return a;
}
__device__ __forceinline__ void cp16(uint32_t sdst, const void* gsrc) {
    asm volatile("cp.async.cg.shared.global [%0], [%1], 16;" :: "r"(sdst), "l"(gsrc));
}
#define CP_COMMIT() asm volatile("cp.async.commit_group;" ::: "memory")
#define CP_WAIT(n)  asm volatile("cp.async.wait_group %0;" :: "n"(n) : "memory")

__device__ __forceinline__ void split2bf(float v, uint16_t& h, uint16_t& l) {
    __nv_bfloat16 hb = __float2bfloat16(v);
    float r = v - __bfloat162float(hb);
    __nv_bfloat16 lb = __float2bfloat16(r);
    h = *reinterpret_cast<uint16_t*>(&hb);
    l = *reinterpret_cast<uint16_t*>(&lb);
}
__device__ __forceinline__ uint32_t pr(uint16_t lo, uint16_t hi) {
    return (uint32_t)lo | ((uint32_t)hi << 16);
}

// ===================== tcgen05/TMA machinery (sm_103a cubin only) =============
#if defined(__CUDA_ARCH_FEAT_SM103_ALL)
__device__ __forceinline__ uint32_t elect_one() {
    uint32_t p;
    asm volatile("{\n\t.reg .pred p;\n\telect.sync _|p, 0xFFFFFFFF;\n\tselp.b32 %0, 1, 0, p;\n\t}"
                 : "=r"(p));
    return p;
}
#define MBARRIER_INIT(addr, cnt) \
    asm volatile("mbarrier.init.shared.b64 [%0], %1;" :: "r"(addr), "r"(cnt) : "memory")
#define MBARRIER_EXPECT_TX(mbar, bytes) \
    asm volatile("mbarrier.arrive.expect_tx.shared.b64 _, [%0], %1;" \
                 :: "r"((uint32_t)(mbar)), "r"((uint32_t)(bytes)) : "memory")
#define MBARRIER_WAIT_PARITY(mbar, par) do {                                             \
    uint32_t _m = (uint32_t)(mbar); uint32_t _p = (uint32_t)(par); uint32_t _d;          \
    asm volatile("{\n\t.reg .pred p;\n\t"                                                \
        "mbarrier.try_wait.parity.acquire.cta.shared::cta.b64 p, [%1], %2;\n\t"          \
        "selp.b32 %0, 1, 0, p;\n\t}" : "=r"(_d) : "r"(_m), "r"(_p) : "memory");          \
    if (!_d) {                                                                           \
        asm volatile("{\n\t.reg .pred P1;\n\tWL_%=: \n\t"                                \
            "mbarrier.try_wait.parity.acquire.cta.shared::cta.b64 P1, [%0], %1, 0x989680;\n\t" \
            "@P1 bra.uni WD_%=;\n\tbra.uni WL_%=;\n\tWD_%=: \n\t}"                       \
            :: "r"(_m), "r"(_p) : "memory");                                             \
    }                                                                                    \
} while (0)
// cg2 TMA: both CTAs execute; complete_tx targets leader (rank0) barrier via bit-24 mask
#define TMA_LOAD_3D_CG2(smem_addr, tmap, c0, c1, c2, mbar) \
    asm volatile( \
        "{\n\t.reg .b32 lb;\n\t" \
        "and.b32 lb, %5, 0xFEFFFFFF;\n\t" \
        "cp.async.bulk.tensor.3d.cta_group::2.shared::cluster.global" \
        ".tile.mbarrier::complete_tx::bytes " \
        "[%0], [%1, {%2, %3, %4}], [lb];\n\t}" \
        :: "r"((uint32_t)(smem_addr)), "l"(tmap), \
           "r"((int)(c0)), "r"((int)(c1)), "r"((int)(c2)), \
           "r"((uint32_t)(mbar)) : "memory")
#define TCGEN05_ALLOC_CG2(sa, n) \
    asm volatile("tcgen05.alloc.cta_group::2.sync.aligned.shared::cta.b32 [%0], %1;" \
                 :: "r"((uint32_t)(sa)), "r"((uint32_t)(n)) : "memory")
#define TCGEN05_RELQ_CG2() \
    asm volatile("tcgen05.relinquish_alloc_permit.cta_group::2.sync.aligned;")
#define TCGEN05_DEALLOC_CG2(t, n) \
    asm volatile("tcgen05.dealloc.cta_group::2.sync.aligned.b32 %0, %1;" \
                 :: "r"(t), "r"((uint32_t)(n)))
#define TCGEN05_COMMIT_MC_CG2(mb) \
    asm volatile("tcgen05.commit.cta_group::2.mbarrier::arrive::one.shared::cluster.multicast::cluster.b64 [%0], %1;" \
                 :: "r"((uint32_t)(mb)), "h"((uint16_t)3) : "memory")
#define TCGEN05_FENCE_AFTER()  asm volatile("tcgen05.fence::after_thread_sync;" ::: "memory")
#define TCGEN05_FENCE_BEFORE() asm volatile("tcgen05.fence::before_thread_sync;" ::: "memory")
#define TCGEN05_WAIT_LD()      asm volatile("tcgen05.wait::ld.sync.aligned;" ::: "memory")
#define CLUSTER_ARRIVE() asm volatile("barrier.cluster.arrive.aligned;" ::: "memory")
#define CLUSTER_WAIT()   asm volatile("barrier.cluster.wait.aligned;" ::: "memory")

#define TCGEN05_LD_X32(r, ta) \
    asm volatile( \
        "tcgen05.ld.sync.aligned.32x32b.x32.b32 " \
        "{%0, %1, %2, %3, %4, %5, %6, %7, " \
        " %8, %9, %10, %11, %12, %13, %14, %15, " \
        " %16, %17, %18, %19, %20, %21, %22, %23, " \
        " %24, %25, %26, %27, %28, %29, %30, %31}, [%32];" \
        : "=r"((r)[0]),  "=r"((r)[1]),  "=r"((r)[2]),  "=r"((r)[3]), \
          "=r"((r)[4]),  "=r"((r)[5]),  "=r"((r)[6]),  "=r"((r)[7]), \
          "=r"((r)[8]),  "=r"((r)[9]),  "=r"((r)[10]), "=r"((r)[11]), \
          "=r"((r)[12]), "=r"((r)[13]), "=r"((r)[14]), "=r"((r)[15]), \
          "=r"((r)[16]), "=r"((r)[17]), "=r"((r)[18]), "=r"((r)[19]), \
          "=r"((r)[20]), "=r"((r)[21]), "=r"((r)[22]), "=r"((r)[23]), \
          "=r"((r)[24]), "=r"((r)[25]), "=r"((r)[26]), "=r"((r)[27]), \
          "=r"((r)[28]), "=r"((r)[29]), "=r"((r)[30]), "=r"((r)[31]) \
        : "r"(ta))

static constexpr uint64_t SMEM_DESC_BASE_SW128 =
    (uint64_t(2) << 61) | (uint64_t(1) << 46) | (uint64_t(64) << 32) | (uint64_t(1) << 16);
#define MAKE_SMEM_DESC(ba) (SMEM_DESC_BASE_SW128 | ((uint64_t)((ba) >> 4) & 0x3FFF))

__device__ __forceinline__ void mma_f16_ss_cg2(uint32_t d, uint64_t a, uint64_t b,
                                               uint32_t idesc, uint32_t acc) {
    asm volatile(
        "{\n\t.reg .pred p;\n\tsetp.ne.u32 p, %4, 0;\n\t"
        "tcgen05.mma.cta_group::2.kind::f16 [%0], %1, %2, %3, "
        "{%5, %5, %5, %5, %5, %5, %5, %5}, p;\n\t}"
        :: "r"(d), "l"(a), "l"(b), "r"(idesc), "r"(acc), "r"(0u) : "memory");
}
#else
// family-pass only: ldmatrix/mma.sync helpers
__device__ __forceinline__ void ldm4(uint32_t* r, uint32_t addr) {
    asm volatile("ldmatrix.sync.aligned.m8n8.x4.shared.b16 {%0,%1,%2,%3}, [%4];"
                 : "=r"(r[0]), "=r"(r[1]), "=r"(r[2]), "=r"(r[3]) : "r"(addr));
}
__device__ __forceinline__ void mma16816(float* d, const uint32_t* a, const uint32_t* b) {
    asm volatile(
        "mma.sync.aligned.m16n8k16.row.col.f32.bf16.bf16.f32 "
        "{%0,%1,%2,%3}, {%4,%5,%6,%7}, {%8,%9}, {%0,%1,%2,%3};"
        : "+f"(d[0]), "+f"(d[1]), "+f"(d[2]), "+f"(d[3])
        : "r"(a[0]), "r"(a[1]), "r"(a[2]), "r"(a[3]), "r"(b[0]), "r"(b[1]));
}
#endif

// ===================== merged prep: x and W' -> packed bf16 ====================
// blocks [0,16384): prep_x; blocks [16384,17408): prep_w
__global__ void __launch_bounds__(256) prep_all(
    const float* __restrict__ x, const float* __restrict__ W,
    const float* __restrict__ U, const float* __restrict__ s,
    const float* __restrict__ V)
{
    __shared__ float Us[64][16];
    const int tid = threadIdx.x;

    if (blockIdx.x < 16384) {
        // ---- prep_x ----
        size_t i0  = ((size_t)blockIdx.x * 256 + tid) * 8;   // flat over 8192*4096
        size_t row = i0 >> 12;
        int    k   = (int)(i0 & 4095);
        float4 a = *reinterpret_cast<const float4*>(x + i0);
        float4 b = *reinterpret_cast<const float4*>(x + i0 + 4);
        float v[8] = {a.x, a.y, a.z, a.w, b.x, b.y, b.z, b.w};
        uint16_t h[8], l[8];
        #pragma unroll
        for (int e = 0; e < 8; ++e) split2bf(v[e], h[e], l[e]);
        size_t base = row * PK + (size_t)(k >> 5) * 64 + (k & 31);
        *reinterpret_cast<uint4*>(&g_Xp[base]) =
            make_uint4(pr(h[0], h[1]), pr(h[2], h[3]), pr(h[4], h[5]), pr(h[6], h[7]));
        *reinterpret_cast<uint4*>(&g_Xp[base + 32]) =
            make_uint4(pr(l[0], l[1]), pr(l[2], l[3]), pr(l[4], l[5]), pr(l[6], l[7]));
        return;
    }

    // ---- prep_w ----
    const int bw     = blockIdx.x - 16384;
    const int i_base = (bw & 15) * 256;
    const int o_base = (bw >> 4) * 64;

    for (int t = tid; t < 64 * 16; t += 256) {
        int ol = t >> 4, r = t & 15;
        Us[ol][r] = U[(size_t)(o_base + ol) * RANK + r] * s[r];
    }
    const int i = i_base + tid;
    float4 q0 = *reinterpret_cast<const float4*>(V + (size_t)i * RANK + 0);
    float4 q1 = *reinterpret_cast<const float4*>(V + (size_t)i * RANK + 4);
    float4 q2 = *reinterpret_cast<const float4*>(V + (size_t)i * RANK + 8);
    float4 q3 = *reinterpret_cast<const float4*>(V + (size_t)i * RANK + 12);
    float vr[16] = {q0.x, q0.y, q0.z, q0.w, q1.x, q1.y, q1.z, q1.w,
                    q2.x, q2.y, q2.z, q2.w, q3.x, q3.y, q3.z, q3.w};
    __syncthreads();

    const size_t col_h = (size_t)(i >> 5) * 64 + (i & 31);
    for (int ol = 0; ol < 64; ++ol) {
        const int o = o_base + ol;
        float acc = W[(size_t)o * IN_F + i];
        #pragma unroll
        for (int r = 0; r < 16; ++r) acc += Us[ol][r] * vr[r];
        uint16_t h, l;
        split2bf(acc, h, l);
        g_Wp[(size_t)o * PK + col_h]      = *reinterpret_cast<__nv_bfloat16*>(&h);
        g_Wp[(size_t)o * PK + col_h + 32] = *reinterpret_cast<__nv_bfloat16*>(&l);
    }
}

// ===================== GEMM kernel =====================
// grid (2, 16, 32), cluster (2,1,1), 256 threads.
// cg2 cluster computes 256x256: rank r holds A rows m_base+r*128.., W rows n_base+r*128..
__global__ void __launch_bounds__(THREADS, 1) __cluster_dims__(2, 1, 1)
gemm_kernel(float* __restrict__ out,
            const __grid_constant__ CUtensorMap tmx,
            const __grid_constant__ CUtensorMap tmw)
{
    extern __shared__ char smem[];
    const uint32_t sb = smem_u32(smem);
    const int tid  = threadIdx.x;
    const int lane = tid & 31;
    const int wid  = tid >> 5;
    const int rank   = (int)blockIdx.x;          // cluster rank (cluster spans x)
    const int n_base = (int)blockIdx.y * 256;
    const int m_base = (int)blockIdx.z * 256;

#if defined(__CUDA_ARCH_FEAT_SM103_ALL)
    // ===================== tcgen05 cg2 + TMA path =====================
    const uint32_t FULL = sb + 64;            // 128 stage-full mbarriers (rank0 authoritative)
    const uint32_t MBM  = sb + 2048;          // 128 mma-done mbarriers (multicast commit)

    if (tid == 0) {
        for (int i = 0; i < NK_TC; ++i) {
            MBARRIER_INIT(FULL + i * 8, 1);
            MBARRIER_INIT(MBM + i * 8, 1);
        }
    }
    if (wid == 0) TCGEN05_ALLOC_CG2(sb + 0, 256);
    __syncthreads();
    uint32_t tmem;
    asm volatile("ld.shared.b32 %0, [%1];" : "=r"(tmem) : "r"(sb + 0));

    // cluster barrier: all mbarriers initialized before any cg2 TMA / multicast commit
    CLUSTER_ARRIVE();
    CLUSTER_WAIT();

    const int a_row = m_base + rank * 128;    // this CTA's A slice rows
    const int w_row = n_base + rank * 128;    // this CTA's W slice rows

    if (wid == 0 && elect_one()) {
        if (rank == 0) {
            // prologue: stages 0..3
            #pragma unroll
            for (int p = 0; p < 4; ++p) {
                const uint32_t stb = sb + HDR_TC + p * STG_TC;
                MBARRIER_EXPECT_TX(FULL + p * 8, 2 * STG_TC);   // both CTAs' bytes
                TMA_LOAD_3D_CG2(stb,          &tmx, 64 * p, a_row, 0, FULL + p * 8);
                TMA_LOAD_3D_CG2(stb + SW_OFF, &tmw, 64 * p, w_row, 0, FULL + p * 8);
            }
            for (int it = 0; it < NK_TC; ++it) {
                const int cur = it % NSTAGE;
                MBARRIER_WAIT_PARITY(FULL + it * 8, 0);
                const uint32_t stb = sb + HDR_TC + cur * STG_TC;
                const uint64_t dA  = MAKE_SMEM_DESC(stb);
                const uint64_t dW  = MAKE_SMEM_DESC(stb + SW_OFF);
                const uint32_t first = (it == 0) ? 0u : 1u;
                mma_f16_ss_cg2(tmem, dA + 0, dW + 0, IDESC_CG2, first);  // xh*Wh k0
                mma_f16_ss_cg2(tmem, dA + 2, dW + 2, IDESC_CG2, 1u);     // xh*Wh k1
                mma_f16_ss_cg2(tmem, dA + 0, dW + 4, IDESC_CG2, 1u);     // xh*Wl k0
                mma_f16_ss_cg2(tmem, dA + 2, dW + 6, IDESC_CG2, 1u);     // xh*Wl k1
                mma_f16_ss_cg2(tmem, dA + 4, dW + 0, IDESC_CG2, 1u);     // xl*Wh k0
                mma_f16_ss_cg2(tmem, dA + 6, dW + 2, IDESC_CG2, 1u);     // xl*Wh k1
                TCGEN05_COMMIT_MC_CG2(MBM + it * 8);
                if (it + 4 < NK_TC) {
                    if (it >= 1) MBARRIER_WAIT_PARITY(MBM + (it - 1) * 8, 0);
                    const int    s  = it + 4;
                    const uint32_t nb = sb + HDR_TC + (s % NSTAGE) * STG_TC;
                    MBARRIER_EXPECT_TX(FULL + s * 8, 2 * STG_TC);
                    TMA_LOAD_3D_CG2(nb,          &tmx, 64 * s, a_row, 0, FULL + s * 8);
                    TMA_LOAD_3D_CG2(nb + SW_OFF, &tmw, 64 * s, w_row, 0, FULL + s * 8);
                }
            }
        } else {
            // rank 1: producer only; TMAs complete on rank0's FULL via bit-24 mask
            #pragma unroll
            for (int p = 0; p < 4; ++p) {
                const uint32_t stb = sb + HDR_TC + p * STG_TC;
                TMA_LOAD_3D_CG2(stb,          &tmx, 64 * p, a_row, 0, FULL + p * 8);
                TMA_LOAD_3D_CG2(stb + SW_OFF, &tmw, 64 * p, w_row, 0, FULL + p * 8);
            }
            for (int it = 0; it + 4 < NK_TC; ++it) {
                if (it >= 1) MBARRIER_WAIT_PARITY(MBM + (it - 1) * 8, 0);
                const int    s  = it + 4;
                const uint32_t nb = sb + HDR_TC + (s % NSTAGE) * STG_TC;
                TMA_LOAD_3D_CG2(nb,          &tmx, 64 * s, a_row, 0, FULL + s * 8);
                TMA_LOAD_3D_CG2(nb + SW_OFF, &tmw, 64 * s, w_row, 0, FULL + s * 8);
            }
        }
    }

    // all threads (both CTAs): wait for last MMA (multicast commit)
    MBARRIER_WAIT_PARITY(MBM + (NK_TC - 1) * 8, 0);
    TCGEN05_FENCE_AFTER();

    // epilogue: this CTA's TMEM holds D rows [rank*128, rank*128+128) x 256 cols
    {
        const int sub = wid & 3;
        const int q   = wid >> 2;
        const int row = m_base + rank * 128 + sub * 32 + lane;
        #pragma unroll
        for (int cc = 0; cc < 4; ++cc) {
            uint32_t regs[32];
            const uint32_t col0 = (uint32_t)(q * 128 + cc * 32);
            TCGEN05_LD_X32(regs, tmem + col0);
            TCGEN05_WAIT_LD();
            float* dst = out + (size_t)row * OUT_F + n_base + col0;
            #pragma unroll
            for (int j = 0; j < 32; j += 4)
                *reinterpret_cast<float4*>(dst + j) =
                    make_float4(__uint_as_float(regs[j]), __uint_as_float(regs[j + 1]),
                                __uint_as_float(regs[j + 2]), __uint_as_float(regs[j + 3]));
        }
    }
    TCGEN05_FENCE_BEFORE();
    __syncthreads();
    CLUSTER_ARRIVE();
    CLUSTER_WAIT();
    if (wid == 0) {
        TCGEN05_RELQ_CG2();
        TCGEN05_DEALLOC_CG2(tmem, 256);
    }
    CLUSTER_ARRIVE();
    CLUSTER_WAIT();

#else
    // ============ fallback (mma.sync): this CTA does 128 rows x 256 cols =======
    const int wm = wid & 3;
    const int wn = wid >> 2;
    const int mb = m_base + rank * 128;

    for (int nhalf = 0; nhalf < 2; ++nhalf) {
        const int n_base_fb = n_base + nhalf * 128;
        __syncthreads();   // protect stage reuse across halves

        auto issue = [&](int st, int kidx) {
            const uint32_t stb = sb + st * STG_FB;
            const int g = kidx;
            const int r0 = tid >> 2, c = tid & 3;
            #pragma unroll
            for (int j = 0; j < 2; ++j) {
                int r = r0 + j * 64;
                uint32_t rowoff = (uint32_t)(r * (ROWH * 2) + c * 16);
                size_t bx = (size_t)(mb + r) * PK + (size_t)g * 64 + c * 8;
                size_t bw = (size_t)(n_base_fb + r) * PK + (size_t)g * 64 + c * 8;
                cp16(stb + AH_B + rowoff, &g_Xp[bx]);
                cp16(stb + AL_B + rowoff, &g_Xp[bx + 32]);
                cp16(stb + BH_B + rowoff, &g_Wp[bw]);
                cp16(stb + BL_B + rowoff, &g_Wp[bw + 32]);
            }
        };

        issue(0, 0); CP_COMMIT();
        issue(1, 1); CP_COMMIT();

        float acc[2][8][4];
        #pragma unroll
        for (int a = 0; a < 2; ++a)
            #pragma unroll
            for (int b = 0; b < 8; ++b)
                #pragma unroll
                for (int cidx = 0; cidx < 4; ++cidx) acc[a][b][cidx] = 0.f;

        const int aRow  = wm * 32 + (lane & 15);
        const int aColH = (lane >> 4) * 8;
        const int bIdx  = lane & 7;
        const int bGrp  = lane >> 3;
        const int bRow  = wn * 64 + ((bGrp & 2) << 2) + bIdx;
        const int bColH = (bGrp & 1) * 8;

        for (int i = 0; i < NK_FB; ++i) {
            CP_WAIT(1);
            __syncthreads();
            if (i + 2 < NK_FB) issue((i + 2) % NSTAGE_FB, i + 2);
            CP_COMMIT();

            const uint32_t stb = sb + (i % NSTAGE_FB) * STG_FB;
            #pragma unroll
            for (int k16 = 0; k16 < 2; ++k16) {
                uint32_t ah[2][4], al[2][4];
                #pragma unroll
                for (int mt = 0; mt < 2; ++mt) {
                    uint32_t off = (uint32_t)((aRow + mt * 16) * (ROWH * 2) +
                                              (k16 * 16 + aColH) * 2);
                    ldm4(ah[mt], stb + AH_B + off);
                    ldm4(al[mt], stb + AL_B + off);
                }
                #pragma unroll
                for (int j = 0; j < 4; ++j) {
                    uint32_t off = (uint32_t)((bRow + j * 16) * (ROWH * 2) +
                                              (k16 * 16 + bColH) * 2);
                    uint32_t bh[4];
                    ldm4(bh, stb + BH_B + off);
                    #pragma unroll
                    for (int mt = 0; mt < 2; ++mt) {
                        mma16816(acc[mt][2 * j + 0], ah[mt], bh + 0);
                        mma16816(acc[mt][2 * j + 1], ah[mt], bh + 2);
                        mma16816(acc[mt][2 * j + 0], al[mt], bh + 0);
                        mma16816(acc[mt][2 * j + 1], al[mt], bh + 2);
                    }
                }
                #pragma unroll
                for (int j = 0; j < 4; ++j) {
                    uint32_t off = (uint32_t)((bRow + j * 16) * (ROWH * 2) +
                                              (k16 * 16 + bColH) * 2);
                    uint32_t bl[4];
                    ldm4(bl, stb + BL_B + off);
                    #pragma unroll
                    for (int mt = 0; mt < 2; ++mt) {
                        mma16816(acc[mt][2 * j + 0], ah[mt], bl + 0);
                        mma16816(acc[mt][2 * j + 1], ah[mt], bl + 2);
                    }
                }
            }
        }

        #pragma unroll
        for (int mt = 0; mt < 2; ++mt) {
            const int row0 = mb + wm * 32 + mt * 16 + (lane >> 2);
            #pragma unroll
            for (int nb = 0; nb < 8; ++nb) {
                const int col = n_base_fb + wn * 64 + nb * 8 + (lane & 3) * 2;
                *reinterpret_cast<float2*>(out + (size_t)row0 * OUT_F + col) =
                    make_float2(acc[mt][nb][0], acc[mt][nb][1]);
                *reinterpret_cast<float2*>(out + (size_t)(row0 + 8) * OUT_F + col) =
                    make_float2(acc[mt][nb][2], acc[mt][nb][3]);
            }
        }
    }
#endif
}

// ===================== harness entry =====================
typedef CUresult (*PFN_encodeTiled_t)(
    CUtensorMap*, CUtensorMapDataType, cuuint32_t, void*,
    const cuuint64_t*, const cuuint64_t*, const cuuint32_t*, const cuuint32_t*,
    CUtensorMapInterleave, CUtensorMapSwizzle, CUtensorMapL2promotion,
    CUtensorMapFloatOOBfill);

extern "C" void kernel_launch(void* const* d_in, const int* in_sizes, int n_in,
                              void* d_out, int out_size)
{
    const float* x = (const float*)d_in[0];
    const float* W = (const float*)d_in[1];
    const float* U = (const float*)d_in[2];
    const float* s = (const float*)d_in[3];
    const float* V = (const float*)d_in[4];
    float* out = (float*)d_out;
    (void)in_sizes; (void)n_in; (void)out_size;

    prep_all<<<16384 + 1024, 256>>>(x, W, U, s, V);

    // TMA descriptors (host-side; no allocation; graph-capture safe)
    alignas(64) CUtensorMap tmx{}, tmw{};
    {
        void* px = nullptr; cudaGetSymbolAddress(&px, g_Xp);
        void* pw = nullptr; cudaGetSymbolAddress(&pw, g_Wp);
        PFN_encodeTiled_t enc = nullptr;
        cudaDriverEntryPointQueryResult st{};
        cudaGetDriverEntryPoint("cuTensorMapEncodeTiled", (void**)&enc,
                                cudaEnableDefault, &st);
        if (enc) {
            cuuint32_t box[3] = {64, 128, 1};
            cuuint32_t es[3]  = {1, 1, 1};
            cuuint64_t dimsX[3] = {(cuuint64_t)PK, (cuuint64_t)M_TOTAL, 1};
            cuuint64_t strX[2]  = {(cuuint64_t)PK * 2, (cuuint64_t)PK * 2 * M_TOTAL};
            enc(&tmx, CU_TENSOR_MAP_DATA_TYPE_BFLOAT16, 3, px, dimsX, strX, box, es,
                CU_TENSOR_MAP_INTERLEAVE_NONE, CU_TENSOR_MAP_SWIZZLE_128B,
                CU_TENSOR_MAP_L2_PROMOTION_L2_128B, CU_TENSOR_MAP_FLOAT_OOB_FILL_NONE);
            cuuint64_t dimsW[3] = {(cuuint64_t)PK, (cuuint64_t)OUT_F, 1};
            cuuint64_t strW[2]  = {(cuuint64_t)PK * 2, (cuuint64_t)PK * 2 * OUT_F};
            enc(&tmw, CU_TENSOR_MAP_DATA_TYPE_BFLOAT16, 3, pw, dimsW, strW, box, es,
                CU_TENSOR_MAP_INTERLEAVE_NONE, CU_TENSOR_MAP_SWIZZLE_128B,
                CU_TENSOR_MAP_L2_PROMOTION_L2_128B, CU_TENSOR_MAP_FLOAT_OOB_FILL_NONE);
        }
    }

    cudaFuncSetAttribute(gemm_kernel, cudaFuncAttributeMaxDynamicSharedMemorySize, SMEM_DYN);
    gemm_kernel<<<dim3(2, OUT_F / 256, M_TOTAL / 256), THREADS, SMEM_DYN>>>(out, tmx, tmw);
}

// round 14
// speedup vs baseline: 1.2854x; 1.0772x over previous
#include <cuda_runtime.h>
#include <cuda.h>
#include <cuda_bf16.h>
#include <cstdint>
#include <cstddef>

// ===================== problem constants =====================
static constexpr int IN_F    = 4096;
static constexpr int OUT_F   = 4096;
static constexpr int RANK    = 16;
static constexpr int M_TOTAL = 4 * 2048;     // 8192 rows of x
static constexpr int PK      = 2 * IN_F;     // packed K (hi|lo per 32-group) = 8192

static constexpr int THREADS  = 256;
static constexpr int NCLUST   = 74;          // persistent clusters (148 CTAs)
static constexpr int NTILES   = (M_TOTAL / 256) * (OUT_F / 256);   // 512
static constexpr int M_TILES  = M_TOTAL / 256;                     // 32

// ---- tcgen05 cg2 path ----
static constexpr int KC_TC = 32;             // k-elems per stage
static constexpr int NK_TC = IN_F / KC_TC;   // 128 k-iters per tile
static constexpr int SW_OFF  = 16384;        // W slice offset within stage
static constexpr int STG_TC  = 32768;        // per-CTA stage bytes (X 16K + W 16K)
static constexpr int NSTAGE  = 5;
// header: [0,16) tmem ptr, [64,104) FULL[5], [128,160) MBM[4], [192,208) TILE[2], [256,272) EPI[2]
static constexpr int HDR_TC  = 1024;
static constexpr int SMEM_DYN = HDR_TC + NSTAGE * STG_TC;   // 164864

// idesc cg2 kind::f16: bf16 x bf16 -> f32, M=256, N=256, K-major both
static constexpr uint32_t IDESC_CG2 =
    (1u << 4) | (1u << 7) | (1u << 10) | ((256 / 8u) << 17) | ((256 / 16u) << 24);

// ---- fallback (mma.sync) ----
static constexpr int KC_FB = 32;
static constexpr int NK_FB = IN_F / KC_FB;   // 128
static constexpr int ROWH  = 40;
static constexpr int AH_B  = 0;
static constexpr int AL_B  = 128 * ROWH * 2;
static constexpr int BH_B  = 2 * 128 * ROWH * 2;
static constexpr int BL_B  = 3 * 128 * ROWH * 2;
static constexpr int STG_FB = 4 * 128 * ROWH * 2;    // 40960
static constexpr int NSTAGE_FB = 3;                  // 122880 <= SMEM_DYN

// ===================== scratch (__device__ globals; no cudaMalloc) ===========
__device__ __nv_bfloat16 g_Xp[(size_t)M_TOTAL * PK];   // 128 MB
__device__ __nv_bfloat16 g_Wp[(size_t)OUT_F * PK];     // 64 MB

// ===================== common helpers =====================
__device__ __forceinline__ uint32_t smem_u32(const void* p) {
    uint32_t a;
    asm("{ .reg .u64 t; cvta.to.shared.u64 t, %1; cvt.u32.u64 %0, t; }" : "=r"(a) : "l"(p));
    return a;
}
__device__ __forceinline__ void cp16(uint32_t sdst, const void* gsrc) {
    asm volatile("cp.async.cg.shared.global [%0], [%1], 16;" :: "r"(sdst), "l"(gsrc));
}
#define CP_COMMIT() asm volatile("cp.async.commit_group;" ::: "memory")
#define CP_WAIT(n)  asm volatile("cp.async.wait_group %0;" :: "n"(n) : "memory")

__device__ __forceinline__ void split2bf(float v, uint16_t& h, uint16_t& l) {
    __nv_bfloat16 hb = __float2bfloat16(v);
    float r = v - __bfloat162float(hb);
    __nv_bfloat16 lb = __float2bfloat16(r);
    h = *reinterpret_cast<uint16_t*>(&hb);
    l = *reinterpret_cast<uint16_t*>(&lb);
}
__device__ __forceinline__ uint32_t pr(uint16_t lo, uint16_t hi) {
    return (uint32_t)lo | ((uint32_t)hi << 16);
}

// ===================== tcgen05/TMA machinery (sm_103a cubin only) =============
#if defined(__CUDA_ARCH_FEAT_SM103_ALL)
__device__ __forceinline__ uint32_t elect_one() {
    uint32_t p;
    asm volatile("{\n\t.reg .pred p;\n\telect.sync _|p, 0xFFFFFFFF;\n\tselp.b32 %0, 1, 0, p;\n\t}"
                 : "=r"(p));
    return p;
}
#define MBARRIER_INIT(addr, cnt) \
    asm volatile("mbarrier.init.shared.b64 [%0], %1;" :: "r"(addr), "r"(cnt) : "memory")
#define MBARRIER_ARRIVE(mbar) \
    asm volatile("mbarrier.arrive.shared.b64 _, [%0];" :: "r"((uint32_t)(mbar)) : "memory")
#define MBARRIER_ARRIVE_CLUSTER(mbar, trank) \
    asm volatile("{\n\t.reg .b32 ra;\n\t" \
                 "mapa.shared::cluster.u32 ra, %0, %1;\n\t" \
                 "mbarrier.arrive.shared::cluster.b64 _, [ra];\n\t}" \
                 :: "r"((uint32_t)(mbar)), "r"((uint32_t)(trank)) : "memory")
#define MBARRIER_EXPECT_TX(mbar, bytes) \
    asm volatile("mbarrier.arrive.expect_tx.shared.b64 _, [%0], %1;" \
                 :: "r"((uint32_t)(mbar)), "r"((uint32_t)(bytes)) : "memory")
#define MBARRIER_WAIT_PARITY(mbar, par) do {                                             \
    uint32_t _m = (uint32_t)(mbar); uint32_t _p = (uint32_t)(par); uint32_t _d;          \
    asm volatile("{\n\t.reg .pred p;\n\t"                                                \
        "mbarrier.try_wait.parity.acquire.cta.shared::cta.b64 p, [%1], %2;\n\t"          \
        "selp.b32 %0, 1, 0, p;\n\t}" : "=r"(_d) : "r"(_m), "r"(_p) : "memory");          \
    if (!_d) {                                                                           \
        asm volatile("{\n\t.reg .pred P1;\n\tWL_%=: \n\t"                                \
            "mbarrier.try_wait.parity.acquire.cta.shared::cta.b64 P1, [%0], %1, 0x989680;\n\t" \
            "@P1 bra.uni WD_%=;\n\tbra.uni WL_%=;\n\tWD_%=: \n\t}"                       \
            :: "r"(_m), "r"(_p) : "memory");                                             \
    }                                                                                    \
} while (0)
#define TMA_LOAD_3D_CG2(smem_addr, tmap, c0, c1, c2, mbar) \
    asm volatile( \
        "{\n\t.reg .b32 lb;\n\t" \
        "and.b32 lb, %5, 0xFEFFFFFF;\n\t" \
        "cp.async.bulk.tensor.3d.cta_group::2.shared::cluster.global" \
        ".tile.mbarrier::complete_tx::bytes " \
        "[%0], [%1, {%2, %3, %4}], [lb];\n\t}" \
        :: "r"((uint32_t)(smem_addr)), "l"(tmap), \
           "r"((int)(c0)), "r"((int)(c1)), "r"((int)(c2)), \
           "r"((uint32_t)(mbar)) : "memory")
#define TCGEN05_ALLOC_CG2(sa, n) \
    asm volatile("tcgen05.alloc.cta_group::2.sync.aligned.shared::cta.b32 [%0], %1;" \
                 :: "r"((uint32_t)(sa)), "r"((uint32_t)(n)) : "memory")
#define TCGEN05_RELQ_CG2() \
    asm volatile("tcgen05.relinquish_alloc_permit.cta_group::2.sync.aligned;")
#define TCGEN05_DEALLOC_CG2(t, n) \
    asm volatile("tcgen05.dealloc.cta_group::2.sync.aligned.b32 %0, %1;" \
                 :: "r"(t), "r"((uint32_t)(n)))
#define TCGEN05_COMMIT_MC_CG2(mb) \
    asm volatile("tcgen05.commit.cta_group::2.mbarrier::arrive::one.shared::cluster.multicast::cluster.b64 [%0], %1;" \
                 :: "r"((uint32_t)(mb)), "h"((uint16_t)3) : "memory")
#define TCGEN05_FENCE_AFTER()  asm volatile("tcgen05.fence::after_thread_sync;" ::: "memory")
#define TCGEN05_FENCE_BEFORE() asm volatile("tcgen05.fence::before_thread_sync;" ::: "memory")
#define TCGEN05_WAIT_LD()      asm volatile("tcgen05.wait::ld.sync.aligned;" ::: "memory")
#define CLUSTER_ARRIVE() asm volatile("barrier.cluster.arrive.aligned;" ::: "memory")
#define CLUSTER_WAIT()   asm volatile("barrier.cluster.wait.aligned;" ::: "memory")

#define TCGEN05_LD_X32(r, ta) \
    asm volatile( \
        "tcgen05.ld.sync.aligned.32x32b.x32.b32 " \
        "{%0, %1, %2, %3, %4, %5, %6, %7, " \
        " %8, %9, %10, %11, %12, %13, %14, %15, " \
        " %16, %17, %18, %19, %20, %21, %22, %23, " \
        " %24, %25, %26, %27, %28, %29, %30, %31}, [%32];" \
        : "=r"((r)[0]),  "=r"((r)[1]),  "=r"((r)[2]),  "=r"((r)[3]), \
          "=r"((r)[4]),  "=r"((r)[5]),  "=r"((r)[6]),  "=r"((r)[7]), \
          "=r"((r)[8]),  "=r"((r)[9]),  "=r"((r)[10]), "=r"((r)[11]), \
          "=r"((r)[12]), "=r"((r)[13]), "=r"((r)[14]), "=r"((r)[15]), \
          "=r"((r)[16]), "=r"((r)[17]), "=r"((r)[18]), "=r"((r)[19]), \
          "=r"((r)[20]), "=r"((r)[21]), "=r"((r)[22]), "=r"((r)[23]), \
          "=r"((r)[24]), "=r"((r)[25]), "=r"((r)[26]), "=r"((r)[27]), \
          "=r"((r)[28]), "=r"((r)[29]), "=r"((r)[30]), "=r"((r)[31]) \
        : "r"(ta))

static constexpr uint64_t SMEM_DESC_BASE_SW128 =
    (uint64_t(2) << 61) | (uint64_t(1) << 46) | (uint64_t(64) << 32) | (uint64_t(1) << 16);
#define MAKE_SMEM_DESC(ba) (SMEM_DESC_BASE_SW128 | ((uint64_t)((ba) >> 4) & 0x3FFF))

__device__ __forceinline__ void mma_f16_ss_cg2(uint32_t d, uint64_t a, uint64_t b,
                                               uint32_t idesc, uint32_t acc) {
    asm volatile(
        "{\n\t.reg .pred p;\n\tsetp.ne.u32 p, %4, 0;\n\t"
        "tcgen05.mma.cta_group::2.kind::f16 [%0], %1, %2, %3, "
        "{%5, %5, %5, %5, %5, %5, %5, %5}, p;\n\t}"
        :: "r"(d), "l"(a), "l"(b), "r"(idesc), "r"(acc), "r"(0u) : "memory");
}
#else
__device__ __forceinline__ void ldm4(uint32_t* r, uint32_t addr) {
    asm volatile("ldmatrix.sync.aligned.m8n8.x4.shared.b16 {%0,%1,%2,%3}, [%4];"
                 : "=r"(r[0]), "=r"(r[1]), "=r"(r[2]), "=r"(r[3]) : "r"(addr));
}
__device__ __forceinline__ void mma16816(float* d, const uint32_t* a, const uint32_t* b) {
    asm volatile(
        "mma.sync.aligned.m16n8k16.row.col.f32.bf16.bf16.f32 "
        "{%0,%1,%2,%3}, {%4,%5,%6,%7}, {%8,%9}, {%0,%1,%2,%3};"
        : "+f"(d[0]), "+f"(d[1]), "+f"(d[2]), "+f"(d[3])
        : "r"(a[0]), "r"(a[1]), "r"(a[2]), "r"(a[3]), "r"(b[0]), "r"(b[1]));
}
#endif

// ===================== merged prep: x and W' -> packed bf16 ====================
__global__ void __launch_bounds__(256) prep_all(
    const float* __restrict__ x, const float* __restrict__ W,
    const float* __restrict__ U, const float* __restrict__ s,
    const float* __restrict__ V)
{
    __shared__ float Us[64][16];
    const int tid = threadIdx.x;

    if (blockIdx.x < 16384) {
        size_t i0  = ((size_t)blockIdx.x * 256 + tid) * 8;
        size_t row = i0 >> 12;
        int    k   = (int)(i0 & 4095);
        float4 a = *reinterpret_cast<const float4*>(x + i0);
        float4 b = *reinterpret_cast<const float4*>(x + i0 + 4);
        float v[8] = {a.x, a.y, a.z, a.w, b.x, b.y, b.z, b.w};
        uint16_t h[8], l[8];
        #pragma unroll
        for (int e = 0; e < 8; ++e) split2bf(v[e], h[e], l[e]);
        size_t base = row * PK + (size_t)(k >> 5) * 64 + (k & 31);
        *reinterpret_cast<uint4*>(&g_Xp[base]) =
            make_uint4(pr(h[0], h[1]), pr(h[2], h[3]), pr(h[4], h[5]), pr(h[6], h[7]));
        *reinterpret_cast<uint4*>(&g_Xp[base + 32]) =
            make_uint4(pr(l[0], l[1]), pr(l[2], l[3]), pr(l[4], l[5]), pr(l[6], l[7]));
        return;
    }

    const int bw     = blockIdx.x - 16384;
    const int i_base = (bw & 15) * 256;
    const int o_base = (bw >> 4) * 64;

    for (int t = tid; t < 64 * 16; t += 256) {
        int ol = t >> 4, r = t & 15;
        Us[ol][r] = U[(size_t)(o_base + ol) * RANK + r] * s[r];
    }
    const int i = i_base + tid;
    float4 q0 = *reinterpret_cast<const float4*>(V + (size_t)i * RANK + 0);
    float4 q1 = *reinterpret_cast<const float4*>(V + (size_t)i * RANK + 4);
    float4 q2 = *reinterpret_cast<const float4*>(V + (size_t)i * RANK + 8);
    float4 q3 = *reinterpret_cast<const float4*>(V + (size_t)i * RANK + 12);
    float vr[16] = {q0.x, q0.y, q0.z, q0.w, q1.x, q1.y, q1.z, q1.w,
                    q2.x, q2.y, q2.z, q2.w, q3.x, q3.y, q3.z, q3.w};
    __syncthreads();

    const size_t col_h = (size_t)(i >> 5) * 64 + (i & 31);
    for (int ol = 0; ol < 64; ++ol) {
        const int o = o_base + ol;
        float acc = W[(size_t)o * IN_F + i];
        #pragma unroll
        for (int r = 0; r < 16; ++r) acc += Us[ol][r] * vr[r];
        uint16_t h, l;
        split2bf(acc, h, l);
        g_Wp[(size_t)o * PK + col_h]      = *reinterpret_cast<__nv_bfloat16*>(&h);
        g_Wp[(size_t)o * PK + col_h + 32] = *reinterpret_cast<__nv_bfloat16*>(&l);
    }
}

// ===================== persistent GEMM kernel =====================
// grid (2, 74, 1), cluster (2,1,1), 256 threads. Each cluster loops over tiles.
__global__ void __launch_bounds__(THREADS, 1) __cluster_dims__(2, 1, 1)
gemm_kernel(float* __restrict__ out,
            const __grid_constant__ CUtensorMap tmx,
            const __grid_constant__ CUtensorMap tmw)
{
    extern __shared__ char smem[];
    const uint32_t sb = smem_u32(smem);
    const int tid  = threadIdx.x;
    const int lane = tid & 31;
    const int wid  = tid >> 5;
    const int rank = (int)blockIdx.x;
    const int cid  = (int)blockIdx.y;             // cluster id 0..73
    const int NLOC = (NTILES - 1 - cid) / NCLUST + 1;   // 6 or 7 local tiles

#if defined(__CUDA_ARCH_FEAT_SM103_ALL)
    const uint32_t FULL = sb + 64;    // 5 slots
    const uint32_t MBM  = sb + 128;   // 4 slots
    const uint32_t TILE = sb + 192;   // 2 slots (tile-done, multicast)
    const uint32_t EPI  = sb + 256;   // 2 slots (buffer free, count 2, on rank0)

    if (tid == 0) {
        for (int i = 0; i < 5; ++i) MBARRIER_INIT(FULL + i * 8, 1);
        for (int i = 0; i < 4; ++i) MBARRIER_INIT(MBM + i * 8, 1);
        for (int i = 0; i < 2; ++i) MBARRIER_INIT(TILE + i * 8, 1);
        for (int i = 0; i < 2; ++i) MBARRIER_INIT(EPI + i * 8, 2);
    }
    if (wid == 0) TCGEN05_ALLOC_CG2(sb + 0, 512);   // two 256-col accumulators
    __syncthreads();
    uint32_t tmem;
    asm volatile("ld.shared.b32 %0, [%1];" : "=r"(tmem) : "r"(sb + 0));

    CLUSTER_ARRIVE();
    CLUSTER_WAIT();

    const int L = NLOC * NK_TC;                   // local k-iterations

    // coordinates of local iteration g: tile j = g>>7, k-group = g&127
    // tile id t = cid + 74*j; m_base = (t%32)*256; n_base = (t/32)*256
    auto tma_pair = [&](int g, uint32_t stb, uint32_t mbar) {
        const int j = g >> 7, k = g & 127;
        const int t = cid + NCLUST * j;
        const int a_row = (t % M_TILES) * 256 + rank * 128;
        const int w_row = (t / M_TILES) * 256 + rank * 128;
        TMA_LOAD_3D_CG2(stb,          &tmx, 64 * k, a_row, 0, mbar);
        TMA_LOAD_3D_CG2(stb + SW_OFF, &tmw, 64 * k, w_row, 0, mbar);
    };

    if (wid == 0 && elect_one()) {
        if (rank == 0) {
            // prologue: stages for g = 0..3
            #pragma unroll
            for (int p = 0; p < 4 && p < L; ++p) {
                MBARRIER_EXPECT_TX(FULL + p * 8, 2 * STG_TC);
                tma_pair(p, sb + HDR_TC + p * STG_TC, FULL + p * 8);
            }
            for (int g = 0; g < L; ++g) {
                const int tl = g >> 7, k = g & 127;
                if (k == 0 && tl >= 2)
                    MBARRIER_WAIT_PARITY(EPI + (tl & 1) * 8, ((tl >> 1) - 1) & 1);
                MBARRIER_WAIT_PARITY(FULL + (g % 5) * 8, (g / 5) & 1);
                const uint32_t stb = sb + HDR_TC + (g % NSTAGE) * STG_TC;
                const uint64_t dA  = MAKE_SMEM_DESC(stb);
                const uint64_t dW  = MAKE_SMEM_DESC(stb + SW_OFF);
                const uint32_t D   = tmem + (tl & 1) * 256;
                const uint32_t first = (k == 0) ? 0u : 1u;
                mma_f16_ss_cg2(D, dA + 0, dW + 0, IDESC_CG2, first);
                mma_f16_ss_cg2(D, dA + 2, dW + 2, IDESC_CG2, 1u);
                mma_f16_ss_cg2(D, dA + 0, dW + 4, IDESC_CG2, 1u);
                mma_f16_ss_cg2(D, dA + 2, dW + 6, IDESC_CG2, 1u);
                mma_f16_ss_cg2(D, dA + 4, dW + 0, IDESC_CG2, 1u);
                mma_f16_ss_cg2(D, dA + 6, dW + 2, IDESC_CG2, 1u);
                TCGEN05_COMMIT_MC_CG2(MBM + (g % 4) * 8);
                if (k == 127) TCGEN05_COMMIT_MC_CG2(TILE + (tl & 1) * 8);
                const int nxt = g + 4;
                if (nxt < L) {
                    if (g >= 1) MBARRIER_WAIT_PARITY(MBM + ((g - 1) % 4) * 8, ((g - 1) / 4) & 1);
                    MBARRIER_EXPECT_TX(FULL + (nxt % 5) * 8, 2 * STG_TC);
                    tma_pair(nxt, sb + HDR_TC + (nxt % NSTAGE) * STG_TC, FULL + (nxt % 5) * 8);
                }
            }
        } else {
            // rank 1: producer only
            #pragma unroll
            for (int p = 0; p < 4 && p < L; ++p)
                tma_pair(p, sb + HDR_TC + p * STG_TC, FULL + p * 8);
            for (int g = 0; g + 4 < L; ++g) {
                if (g >= 1) MBARRIER_WAIT_PARITY(MBM + ((g - 1) % 4) * 8, ((g - 1) / 4) & 1);
                const int nxt = g + 4;
                tma_pair(nxt, sb + HDR_TC + (nxt % NSTAGE) * STG_TC, FULL + (nxt % 5) * 8);
            }
        }
    }

    // consumers: warps 4-7 of both CTAs drain finished accumulators
    if (wid >= 4) {
        const int sub = wid - 4;                  // TMEM subpartition (wid % 4)
        for (int tl = 0; tl < NLOC; ++tl) {
            MBARRIER_WAIT_PARITY(TILE + (tl & 1) * 8, (tl >> 1) & 1);
            TCGEN05_FENCE_AFTER();
            const int t = cid + NCLUST * tl;
            const int row = (t % M_TILES) * 256 + rank * 128 + sub * 32 + lane;
            const int n_b = (t / M_TILES) * 256;
            const uint32_t D = tmem + (tl & 1) * 256;
            #pragma unroll
            for (int cc = 0; cc < 8; ++cc) {
                uint32_t regs[32];
                TCGEN05_LD_X32(regs, D + cc * 32);
                TCGEN05_WAIT_LD();
                float* dst = out + (size_t)row * OUT_F + n_b + cc * 32;
                #pragma unroll
                for (int q = 0; q < 32; q += 4)
                    *reinterpret_cast<float4*>(dst + q) =
                        make_float4(__uint_as_float(regs[q]), __uint_as_float(regs[q + 1]),
                                    __uint_as_float(regs[q + 2]), __uint_as_float(regs[q + 3]));
            }
            TCGEN05_FENCE_BEFORE();
            asm volatile("bar.sync 1, 128;" ::: "memory");   // warps 4-7 of this CTA
            if (tid == 128) {                                 // one arrive per CTA
                if (rank == 0) MBARRIER_ARRIVE(EPI + (tl & 1) * 8);
                else           MBARRIER_ARRIVE_CLUSTER(EPI + (tl & 1) * 8, 0);
            }
        }
    }

    __syncthreads();
    CLUSTER_ARRIVE();
    CLUSTER_WAIT();
    if (wid == 0) {
        TCGEN05_RELQ_CG2();
        TCGEN05_DEALLOC_CG2(tmem, 512);
    }
    CLUSTER_ARRIVE();
    CLUSTER_WAIT();

#else
    // ============ fallback (mma.sync): persistent tile loop ====================
    const int wm = wid & 3;
    const int wn = wid >> 2;

    for (int tl = 0; tl < NLOC; ++tl) {
        const int t = cid + NCLUST * tl;
        const int mb  = (t % M_TILES) * 256 + rank * 128;
        const int n_b = (t / M_TILES) * 256;

        for (int nhalf = 0; nhalf < 2; ++nhalf) {
            const int n_base_fb = n_b + nhalf * 128;
            __syncthreads();

            auto issue = [&](int st, int kidx) {
                const uint32_t stb = sb + st * STG_FB;
                const int g = kidx;
                const int r0 = tid >> 2, c = tid & 3;
                #pragma unroll
                for (int j = 0; j < 2; ++j) {
                    int r = r0 + j * 64;
                    uint32_t rowoff = (uint32_t)(r * (ROWH * 2) + c * 16);
                    size_t bx = (size_t)(mb + r) * PK + (size_t)g * 64 + c * 8;
                    size_t bw = (size_t)(n_base_fb + r) * PK + (size_t)g * 64 + c * 8;
                    cp16(stb + AH_B + rowoff, &g_Xp[bx]);
                    cp16(stb + AL_B + rowoff, &g_Xp[bx + 32]);
                    cp16(stb + BH_B + rowoff, &g_Wp[bw]);
                    cp16(stb + BL_B + rowoff, &g_Wp[bw + 32]);
                }
            };

            issue(0, 0); CP_COMMIT();
            issue(1, 1); CP_COMMIT();

            float acc[2][8][4];
            #pragma unroll
            for (int a = 0; a < 2; ++a)
                #pragma unroll
                for (int b = 0; b < 8; ++b)
                    #pragma unroll
                    for (int cidx = 0; cidx < 4; ++cidx) acc[a][b][cidx] = 0.f;

            const int aRow  = wm * 32 + (lane & 15);
            const int aColH = (lane >> 4) * 8;
            const int bIdx  = lane & 7;
            const int bGrp  = lane >> 3;
            const int bRow  = wn * 64 + ((bGrp & 2) << 2) + bIdx;
            const int bColH = (bGrp & 1) * 8;

            for (int i = 0; i < NK_FB; ++i) {
                CP_WAIT(1);
                __syncthreads();
                if (i + 2 < NK_FB) issue((i + 2) % NSTAGE_FB, i + 2);
                CP_COMMIT();

                const uint32_t stb = sb + (i % NSTAGE_FB) * STG_FB;
                #pragma unroll
                for (int k16 = 0; k16 < 2; ++k16) {
                    uint32_t ah[2][4], al[2][4];
                    #pragma unroll
                    for (int mt = 0; mt < 2; ++mt) {
                        uint32_t off = (uint32_t)((aRow + mt * 16) * (ROWH * 2) +
                                                  (k16 * 16 + aColH) * 2);
                        ldm4(ah[mt], stb + AH_B + off);
                        ldm4(al[mt], stb + AL_B + off);
                    }
                    #pragma unroll
                    for (int j = 0; j < 4; ++j) {
                        uint32_t off = (uint32_t)((bRow + j * 16) * (ROWH * 2) +
                                                  (k16 * 16 + bColH) * 2);
                        uint32_t bh[4];
                        ldm4(bh, stb + BH_B + off);
                        #pragma unroll
                        for (int mt = 0; mt < 2; ++mt) {
                            mma16816(acc[mt][2 * j + 0], ah[mt], bh + 0);
                            mma16816(acc[mt][2 * j + 1], ah[mt], bh + 2);
                            mma16816(acc[mt][2 * j + 0], al[mt], bh + 0);
                            mma16816(acc[mt][2 * j + 1], al[mt], bh + 2);
                        }
                    }
                    #pragma unroll
                    for (int j = 0; j < 4; ++j) {
                        uint32_t off = (uint32_t)((bRow + j * 16) * (ROWH * 2) +
                                                  (k16 * 16 + bColH) * 2);
                        uint32_t bl[4];
                        ldm4(bl, stb + BL_B + off);
                        #pragma unroll
                        for (int mt = 0; mt < 2; ++mt) {
                            mma16816(acc[mt][2 * j + 0], ah[mt], bl + 0);
                            mma16816(acc[mt][2 * j + 1], ah[mt], bl + 2);
                        }
                    }
                }
            }

            #pragma unroll
            for (int mt = 0; mt < 2; ++mt) {
                const int row0 = mb + wm * 32 + mt * 16 + (lane >> 2);
                #pragma unroll
                for (int nb = 0; nb < 8; ++nb) {
                    const int col = n_base_fb + wn * 64 + nb * 8 + (lane & 3) * 2;
                    *reinterpret_cast<float2*>(out + (size_t)row0 * OUT_F + col) =
                        make_float2(acc[mt][nb][0], acc[mt][nb][1]);
                    *reinterpret_cast<float2*>(out + (size_t)(row0 + 8) * OUT_F + col) =
                        make_float2(acc[mt][nb][2], acc[mt][nb][3]);
                }
            }
        }
    }
#endif
}

// ===================== harness entry =====================
typedef CUresult (*PFN_encodeTiled_t)(
    CUtensorMap*, CUtensorMapDataType, cuuint32_t, void*,
    const cuuint64_t*, const cuuint64_t*, const cuuint32_t*, const cuuint32_t*,
    CUtensorMapInterleave, CUtensorMapSwizzle, CUtensorMapL2promotion,
    CUtensorMapFloatOOBfill);

extern "C" void kernel_launch(void* const* d_in, const int* in_sizes, int n_in,
                              void* d_out, int out_size)
{
    const float* x = (const float*)d_in[0];
    const float* W = (const float*)d_in[1];
    const float* U = (const float*)d_in[2];
    const float* s = (const float*)d_in[3];
    const float* V = (const float*)d_in[4];
    float* out = (float*)d_out;
    (void)in_sizes; (void)n_in; (void)out_size;

    prep_all<<<16384 + 1024, 256>>>(x, W, U, s, V);

    alignas(64) CUtensorMap tmx{}, tmw{};
    {
        void* px = nullptr; cudaGetSymbolAddress(&px, g_Xp);
        void* pw = nullptr; cudaGetSymbolAddress(&pw, g_Wp);
        PFN_encodeTiled_t enc = nullptr;
        cudaDriverEntryPointQueryResult st{};
        cudaGetDriverEntryPoint("cuTensorMapEncodeTiled", (void**)&enc,
                                cudaEnableDefault, &st);
        if (enc) {
            cuuint32_t box[3] = {64, 128, 1};
            cuuint32_t es[3]  = {1, 1, 1};
            cuuint64_t dimsX[3] = {(cuuint64_t)PK, (cuuint64_t)M_TOTAL, 1};
            cuuint64_t strX[2]  = {(cuuint64_t)PK * 2, (cuuint64_t)PK * 2 * M_TOTAL};
            enc(&tmx, CU_TENSOR_MAP_DATA_TYPE_BFLOAT16, 3, px, dimsX, strX, box, es,
                CU_TENSOR_MAP_INTERLEAVE_NONE, CU_TENSOR_MAP_SWIZZLE_128B,
                CU_TENSOR_MAP_L2_PROMOTION_L2_128B, CU_TENSOR_MAP_FLOAT_OOB_FILL_NONE);
            cuuint64_t dimsW[3] = {(cuuint64_t)PK, (cuuint64_t)OUT_F, 1};
            cuuint64_t strW[2]  = {(cuuint64_t)PK * 2, (cuuint64_t)PK * 2 * OUT_F};
            enc(&tmw, CU_TENSOR_MAP_DATA_TYPE_BFLOAT16, 3, pw, dimsW, strW, box, es,
                CU_TENSOR_MAP_INTERLEAVE_NONE, CU_TENSOR_MAP_SWIZZLE_128B,
                CU_TENSOR_MAP_L2_PROMOTION_L2_128B, CU_TENSOR_MAP_FLOAT_OOB_FILL_NONE);
        }
    }

    cudaFuncSetAttribute(gemm_kernel, cudaFuncAttributeMaxDynamicSharedMemorySize, SMEM_DYN);
    gemm_kernel<<<dim3(2, NCLUST, 1), THREADS, SMEM_DYN>>>(out, tmx, tmw);
}